// round 2
// baseline (speedup 1.0000x reference)
#include <cuda_runtime.h>
#include <cuda_bf16.h>
#include <math.h>
#include <stdint.h>

// ---------------- problem constants ----------------
#define BB 8
#define NN 64
#define IN_DIM 16
#define EDGE_DIM 8
#define DD 128
#define HH 4
#define DHH 32
#define LL 3
#define FF 512
#define MROWS (BB*NN*NN)          // 32768
static const float INV_SCALE = 0.17677669529663687f; // 1/sqrt(32)

// ---------------- scratch (device globals; no runtime alloc) ----------------
__device__ float g_tok  [(size_t)MROWS*DD];
__device__ float g_qkv  [(size_t)MROWS*512];          // q|k|v1|v2 packed along N
__device__ float g_o    [(size_t)MROWS*DD];
__device__ float g_hid  [(size_t)MROWS*FF];
__device__ float g_s    [(size_t)BB*HH*NN*NN*NN];     // [b][h][l][i][j]
__device__ float g_wpack[(size_t)LL*DD*512];          // per-layer packed QKV weights
__device__ int   g_mask_mode;                          // 0=int32, 1=uint8, 2=float32

// ---------------- mask dtype detector ----------------
__global__ void detect_mask_kernel(const unsigned char* __restrict__ m) {
    __shared__ int has3f, hasodd;
    if (threadIdx.x == 0) { has3f = 0; hasodd = 0; }
    __syncthreads();
    for (int i = threadIdx.x; i < 4096; i += blockDim.x) {
        unsigned char v = m[i];
        if (v == 0x3F) atomicOr(&has3f, 1);
        if (v != 0 && (i & 3)) atomicOr(&hasodd, 1);
    }
    __syncthreads();
    if (threadIdx.x == 0) g_mask_mode = has3f ? 2 : (hasodd ? 1 : 0);
}

// ---------------- pack Wq|Wk|Wv1|Wv2 -> [l][k][512] ----------------
__global__ void pack_qkv_kernel(const float* __restrict__ Wq, const float* __restrict__ Wk,
                                const float* __restrict__ Wv1, const float* __restrict__ Wv2) {
    int l  = blockIdx.x >> 7;      // /128
    int kk = blockIdx.x & 127;
    int n  = threadIdx.x;          // 0..511
    int which = n >> 7, col = n & 127;
    const float* src = (which == 0) ? Wq : (which == 1) ? Wk : (which == 2) ? Wv1 : Wv2;
    g_wpack[((size_t)l*DD + kk)*512 + n] = src[((size_t)l*DD + kk)*DD + col];
}

// ---------------- embedding ----------------
__global__ void embed_kernel(const float* __restrict__ x,
                             const float* __restrict__ ea,
                             const void*  __restrict__ mask,
                             const float* __restrict__ nW, const float* __restrict__ nb,
                             const float* __restrict__ eW, const float* __restrict__ eb,
                             const float* __restrict__ noe) {
    int idx = blockIdx.x;                 // b*N*N + i*N + j
    int j = idx & 63;
    int i = (idx >> 6) & 63;
    int b = idx >> 12;
    int d = threadIdx.x;                  // 0..127
    __shared__ float sx[IN_DIM];
    __shared__ float se[EDGE_DIM];
    if (threadIdx.x < IN_DIM)  sx[threadIdx.x] = x[(b*NN + i)*IN_DIM + threadIdx.x];
    if (threadIdx.x < EDGE_DIM) se[threadIdx.x] = ea[((size_t)idx)*EDGE_DIM + threadIdx.x];
    __syncthreads();
    float v;
    if (i == j) {
        v = nb[d];
        #pragma unroll
        for (int e = 0; e < IN_DIM; e++) v = fmaf(sx[e], nW[e*DD + d], v);
    } else {
        bool m;
        int mm = g_mask_mode;
        if (mm == 0)      m = ((const int*)mask)[idx] != 0;
        else if (mm == 1) m = ((const unsigned char*)mask)[idx] != 0;
        else              m = ((const float*)mask)[idx] != 0.f;
        if (m) {
            v = eb[d];
            #pragma unroll
            for (int e = 0; e < EDGE_DIM; e++) v = fmaf(se[e], eW[e*DD + d], v);
        } else {
            v = noe[d];
        }
    }
    g_tok[(size_t)idx*DD + d] = v;
}

// ---------------- SGEMM: C[M,N] = A[M,K] @ W[K,N] (+bias)(+res)(relu | LN) --------
// BM=BN=128, BK=8, 256 threads, 8x8 microtile, float4 smem loads.
// LN epilogue requires N==128 (block owns full rows).
__global__ __launch_bounds__(256)
void gemm_kernel(const float* __restrict__ A, const float* __restrict__ W,
                 const float* __restrict__ bias, const float* __restrict__ res,
                 const float* __restrict__ lng, const float* __restrict__ lnb,
                 float* __restrict__ C, int M, int N, int K, int relu) {
    __shared__ float As[8][132];   // [k][m], padded (+4) to kill STS conflicts
    __shared__ float Bs[8][128];   // [k][n]
    int t  = threadIdx.x;
    int bn = blockIdx.x * 128;
    int bm = blockIdx.y * 128;
    int tm = t >> 4, tn = t & 15;
    int arow = t >> 1,  acol = (t & 1) << 2;   // A: 128 rows x 2 float4
    int brow = t >> 5,  bcol = (t & 31) << 2;  // B: 8 rows x 32 float4
    const float* Aptr = A + (size_t)(bm + arow) * K + acol;
    const float* Bptr = W + (size_t)brow * N + bn + bcol;
    float acc[8][8] = {};
    for (int k0 = 0; k0 < K; k0 += 8) {
        float4 av = *(const float4*)(Aptr + k0);
        float4 bv = *(const float4*)(Bptr + (size_t)k0 * N);
        __syncthreads();
        As[acol+0][arow] = av.x; As[acol+1][arow] = av.y;
        As[acol+2][arow] = av.z; As[acol+3][arow] = av.w;
        *(float4*)&Bs[brow][bcol] = bv;
        __syncthreads();
        #pragma unroll
        for (int k = 0; k < 8; k++) {
            float a[8], b[8];
            *(float4*)(a)   = *(const float4*)&As[k][tm*8];
            *(float4*)(a+4) = *(const float4*)&As[k][tm*8+4];
            *(float4*)(b)   = *(const float4*)&Bs[k][tn*8];
            *(float4*)(b+4) = *(const float4*)&Bs[k][tn*8+4];
            #pragma unroll
            for (int i = 0; i < 8; i++)
                #pragma unroll
                for (int j = 0; j < 8; j++)
                    acc[i][j] = fmaf(a[i], b[j], acc[i][j]);
        }
    }
    // ---------------- epilogue ----------------
    int n0 = bn + tn*8;
    float bi[8];
    if (bias) {
        *(float4*)(bi)   = *(const float4*)(bias + n0);
        *(float4*)(bi+4) = *(const float4*)(bias + n0 + 4);
    }
    float gg[8], gb[8];
    if (lng) {
        *(float4*)(gg)   = *(const float4*)(lng + n0);
        *(float4*)(gg+4) = *(const float4*)(lng + n0 + 4);
        *(float4*)(gb)   = *(const float4*)(lnb + n0);
        *(float4*)(gb+4) = *(const float4*)(lnb + n0 + 4);
    }
    #pragma unroll
    for (int i = 0; i < 8; i++) {
        int m = bm + tm*8 + i;
        size_t off = (size_t)m*N + n0;
        float v[8];
        #pragma unroll
        for (int j = 0; j < 8; j++) v[j] = acc[i][j];
        if (bias) {
            #pragma unroll
            for (int j = 0; j < 8; j++) v[j] += bi[j];
        }
        if (res) {
            float4 r0 = *(const float4*)(res + off);
            float4 r1 = *(const float4*)(res + off + 4);
            v[0]+=r0.x; v[1]+=r0.y; v[2]+=r0.z; v[3]+=r0.w;
            v[4]+=r1.x; v[5]+=r1.y; v[6]+=r1.z; v[7]+=r1.w;
        }
        if (relu) {
            #pragma unroll
            for (int j = 0; j < 8; j++) v[j] = fmaxf(v[j], 0.f);
        }
        if (lng) {
            // row reduce over the 16 tn-lanes (within half-warps: xor 8,4,2,1)
            float s = 0.f;
            #pragma unroll
            for (int j = 0; j < 8; j++) s += v[j];
            #pragma unroll
            for (int o = 8; o > 0; o >>= 1) s += __shfl_xor_sync(0xffffffffu, s, o);
            float mean = s * 0.0078125f;
            float s2 = 0.f;
            #pragma unroll
            for (int j = 0; j < 8; j++) { float c = v[j] - mean; s2 += c*c; }
            #pragma unroll
            for (int o = 8; o > 0; o >>= 1) s2 += __shfl_xor_sync(0xffffffffu, s2, o);
            float rstd = rsqrtf(s2 * 0.0078125f + 1e-5f);
            #pragma unroll
            for (int j = 0; j < 8; j++) v[j] = (v[j] - mean) * rstd * gg[j] + gb[j];
        }
        *(float4*)(C + off)     = make_float4(v[0], v[1], v[2], v[3]);
        *(float4*)(C + off + 4) = make_float4(v[4], v[5], v[6], v[7]);
    }
}

// ---------------- scores: s[b,h,l,i,j] = (1/SCALE) * q[b,i,l,h,:] . k[b,l,j,h,:] ------
__global__ __launch_bounds__(256)
void score_kernel() {
    int bid = blockIdx.x;                  // ((b*H+h)*64 + l)
    int l = bid & 63;
    int h = (bid >> 6) & 3;
    int b = bid >> 8;
    __shared__ float Qs[64][33];
    __shared__ float Ks[64][33];
    int t = threadIdx.x;
    for (int idx = t; idx < 64*32; idx += 256) {
        int r = idx >> 5, c = idx & 31;
        Qs[r][c] = g_qkv[((size_t)((b*NN + r)*NN + l))*512 +       h*DHH + c]; // q, r=i
        Ks[r][c] = g_qkv[((size_t)((b*NN + l)*NN + r))*512 + 128 + h*DHH + c]; // k, r=j
    }
    __syncthreads();
    int tj = t & 15, ti = t >> 4;
    float acc[4][4] = {};
    #pragma unroll
    for (int c = 0; c < 32; c++) {
        float q[4], k[4];
        #pragma unroll
        for (int u = 0; u < 4; u++) { q[u] = Qs[ti*4+u][c]; k[u] = Ks[tj*4+u][c]; }
        #pragma unroll
        for (int i2 = 0; i2 < 4; i2++)
            #pragma unroll
            for (int j2 = 0; j2 < 4; j2++)
                acc[i2][j2] = fmaf(q[i2], k[j2], acc[i2][j2]);
    }
    float* dst = g_s + (size_t)bid * 4096;
    #pragma unroll
    for (int i2 = 0; i2 < 4; i2++)
        #pragma unroll
        for (int j2 = 0; j2 < 4; j2++)
            dst[(ti*4+i2)*64 + tj*4+j2] = acc[i2][j2] * INV_SCALE;
}

// ---------------- softmax over l, in place on g_s[b][h][l][i][j] ----------------
__global__ __launch_bounds__(64)
void softmax_kernel() {
    int bid = blockIdx.x;            // (b*H+h)*64 + i
    int i  = bid & 63;
    int bh = bid >> 6;
    int j  = threadIdx.x;
    size_t base = (size_t)bh * 262144 + (size_t)i*64 + j;
    float v[64];
    float mx = -1e30f;
    #pragma unroll
    for (int l = 0; l < 64; l++) { v[l] = g_s[base + (size_t)l*4096]; mx = fmaxf(mx, v[l]); }
    float s = 0.f;
    #pragma unroll
    for (int l = 0; l < 64; l++) { v[l] = __expf(v[l] - mx); s += v[l]; }
    float inv = 1.f / s;
    #pragma unroll
    for (int l = 0; l < 64; l++) g_s[base + (size_t)l*4096] = v[l] * inv;
}

// ---------------- o[b,i,j,h,d] = sum_l a[b,h,l,i,j]*v1[b,i,l,h,d]*v2[b,l,j,h,d] ------
__global__ __launch_bounds__(256)
void attn_o_kernel() {
    int h = blockIdx.x & 3;
    int i = (blockIdx.x >> 2) & 63;
    int b = blockIdx.x >> 8;
    __shared__ float v1s[64][36];    // [l][dd]
    __shared__ float as[64][64];     // [l][j]
    int t = threadIdx.x;
    for (int idx = t; idx < 64*32; idx += 256) {
        int l = idx >> 5, c = idx & 31;
        v1s[l][c] = g_qkv[((size_t)((b*NN + i)*NN + l))*512 + 256 + h*DHH + c];
    }
    for (int idx = t; idx < 4096; idx += 256) {
        int l = idx >> 6, j = idx & 63;
        as[l][j] = g_s[(size_t)((b*HH + h)*NN + l)*4096 + i*64 + j];
    }
    __syncthreads();
    int td = t & 7;                  // d4 index
    int tj = t >> 3;                 // 0..31
    int j0 = tj, j1 = tj + 32;
    float4 acc0 = {0,0,0,0}, acc1 = {0,0,0,0};
    #pragma unroll 4
    for (int l = 0; l < 64; l++) {
        float a0 = as[l][j0];
        float a1 = as[l][j1];
        float4 v1v = *(const float4*)&v1s[l][td*4];
        const float* base = g_qkv + (size_t)((b*NN + l)*NN)*512 + 384 + h*DHH + td*4;
        float4 w0 = *(const float4*)(base + (size_t)j0*512);
        float4 w1 = *(const float4*)(base + (size_t)j1*512);
        acc0.x = fmaf(a0, v1v.x * w0.x, acc0.x);
        acc0.y = fmaf(a0, v1v.y * w0.y, acc0.y);
        acc0.z = fmaf(a0, v1v.z * w0.z, acc0.z);
        acc0.w = fmaf(a0, v1v.w * w0.w, acc0.w);
        acc1.x = fmaf(a1, v1v.x * w1.x, acc1.x);
        acc1.y = fmaf(a1, v1v.y * w1.y, acc1.y);
        acc1.z = fmaf(a1, v1v.z * w1.z, acc1.z);
        acc1.w = fmaf(a1, v1v.w * w1.w, acc1.w);
    }
    size_t o0 = ((size_t)((b*NN + i)*NN + j0) << 7) + h*DHH + td*4;
    size_t o1 = ((size_t)((b*NN + i)*NN + j1) << 7) + h*DHH + td*4;
    *(float4*)(g_o + o0) = acc0;
    *(float4*)(g_o + o1) = acc1;
}

// ---------------- final: out[b,n] = diag_tok . Wout + bout ----------------
__global__ __launch_bounds__(128)
void out_kernel(const float* __restrict__ Wout, const float* __restrict__ bout,
                float* __restrict__ out) {
    int bn = blockIdx.x;             // b*64 + n
    int n = bn & 63;
    int d = threadIdx.x;
    float v = g_tok[((size_t)bn*NN + n)*DD + d] * Wout[d];
    __shared__ float r[4];
    #pragma unroll
    for (int o = 16; o > 0; o >>= 1) v += __shfl_xor_sync(0xffffffffu, v, o);
    if ((d & 31) == 0) r[d >> 5] = v;
    __syncthreads();
    if (d == 0) out[bn] = r[0] + r[1] + r[2] + r[3] + bout[0];
}

// ---------------- host driver ----------------
extern "C" void kernel_launch(void* const* d_in, const int* in_sizes, int n_in,
                              void* d_out, int out_size) {
    const float* x    = (const float*)d_in[0];
    const float* ea   = (const float*)d_in[1];
    const void*  mask = d_in[2];
    const float* nW   = (const float*)d_in[3];
    const float* nb   = (const float*)d_in[4];
    const float* eW   = (const float*)d_in[5];
    const float* eb   = (const float*)d_in[6];
    const float* noe  = (const float*)d_in[7];
    const float* Wq   = (const float*)d_in[8];
    const float* Wk   = (const float*)d_in[9];
    const float* Wv1  = (const float*)d_in[10];
    const float* Wv2  = (const float*)d_in[11];
    const float* Wo   = (const float*)d_in[12];
    const float* bo   = (const float*)d_in[13];
    const float* ln1g = (const float*)d_in[14];
    const float* ln1b = (const float*)d_in[15];
    const float* W1   = (const float*)d_in[16];
    const float* b1   = (const float*)d_in[17];
    const float* W2   = (const float*)d_in[18];
    const float* b2   = (const float*)d_in[19];
    const float* ln2g = (const float*)d_in[20];
    const float* ln2b = (const float*)d_in[21];
    const float* Wout = (const float*)d_in[22];
    const float* bout = (const float*)d_in[23];

    float *tok, *qkv, *o, *hid, *wpack;
    cudaGetSymbolAddress((void**)&tok,   g_tok);
    cudaGetSymbolAddress((void**)&qkv,   g_qkv);
    cudaGetSymbolAddress((void**)&o,     g_o);
    cudaGetSymbolAddress((void**)&hid,   g_hid);
    cudaGetSymbolAddress((void**)&wpack, g_wpack);

    detect_mask_kernel<<<1, 256>>>((const unsigned char*)mask);
    pack_qkv_kernel<<<LL*DD, 512>>>(Wq, Wk, Wv1, Wv2);
    embed_kernel<<<MROWS, DD>>>(x, ea, mask, nW, nb, eW, eb, noe);

    dim3 gN128(1, MROWS/128);
    dim3 gN512(4, MROWS/128);

    for (int l = 0; l < LL; l++) {
        const float* wp_l  = wpack + (size_t)l*DD*512;
        const float* Wo_l  = Wo  + (size_t)l*DD*DD;
        const float* bo_l  = bo  + (size_t)l*DD;
        const float* g1_l  = ln1g + (size_t)l*DD;
        const float* b1l_l = ln1b + (size_t)l*DD;
        const float* W1_l  = W1  + (size_t)l*DD*FF;
        const float* bf1_l = b1  + (size_t)l*FF;
        const float* W2_l  = W2  + (size_t)l*FF*DD;
        const float* bf2_l = b2  + (size_t)l*DD;
        const float* g2_l  = ln2g + (size_t)l*DD;
        const float* b2l_l = ln2b + (size_t)l*DD;

        // fused QKV projection (q|k|v1|v2)
        gemm_kernel<<<gN512, 256>>>(tok, wp_l, nullptr, nullptr, nullptr, nullptr,
                                    qkv, MROWS, 512, DD, 0);

        score_kernel<<<BB*HH*NN, 256>>>();
        softmax_kernel<<<BB*HH*NN, 64>>>();
        attn_o_kernel<<<BB*NN*HH, 256>>>();

        // o-projection + residual + LN1 (fused epilogue)
        gemm_kernel<<<gN128, 256>>>(o, Wo_l, bo_l, tok, g1_l, b1l_l,
                                    tok, MROWS, DD, DD, 0);
        // FFN up + relu
        gemm_kernel<<<gN512, 256>>>(tok, W1_l, bf1_l, nullptr, nullptr, nullptr,
                                    hid, MROWS, FF, DD, 1);
        // FFN down + residual + LN2 (fused epilogue)
        gemm_kernel<<<gN128, 256>>>(hid, W2_l, bf2_l, tok, g2_l, b2l_l,
                                    tok, MROWS, DD, FF, 0);
    }

    out_kernel<<<BB*NN, 128>>>(Wout, bout, (float*)d_out);
}

// round 5
// speedup vs baseline: 1.6994x; 1.6994x over previous
#include <cuda_runtime.h>
#include <cuda_bf16.h>
#include <math.h>
#include <stdint.h>

// ---------------- problem constants ----------------
#define BB 8
#define NN 64
#define IN_DIM 16
#define EDGE_DIM 8
#define DD 128
#define HH 4
#define DHH 32
#define LL 3
#define FF 512
#define MROWS (BB*NN*NN)          // 32768
static const float INV_SCALE = 0.17677669529663687f; // 1/sqrt(32)

// ---------------- scratch (device globals; no runtime alloc) ----------------
__device__ float g_tok  [(size_t)MROWS*DD];
__device__ float g_qkv  [(size_t)MROWS*512];          // q|k|v1|v2 packed along N
__device__ float g_o    [(size_t)MROWS*DD];
__device__ float g_hid  [(size_t)MROWS*FF];
__device__ float g_s    [(size_t)BB*HH*NN*NN*NN];     // [b][h][l][i][j]
// transposed + bf16-split weights: layout [l][N][K]
__device__ __nv_bfloat16 g_wqkvT_h[(size_t)LL*512*128];
__device__ __nv_bfloat16 g_wqkvT_l[(size_t)LL*512*128];
__device__ __nv_bfloat16 g_woT_h  [(size_t)LL*128*128];
__device__ __nv_bfloat16 g_woT_l  [(size_t)LL*128*128];
__device__ __nv_bfloat16 g_w1T_h  [(size_t)LL*512*128];
__device__ __nv_bfloat16 g_w1T_l  [(size_t)LL*512*128];
__device__ __nv_bfloat16 g_w2T_h  [(size_t)LL*128*512];
__device__ __nv_bfloat16 g_w2T_l  [(size_t)LL*128*512];
__device__ int g_mask_mode;                            // 0=int32, 1=uint8, 2=float32

// ---------------- helpers ----------------
__device__ __forceinline__ void bsplit(float v, __nv_bfloat16& h, __nv_bfloat16& l) {
    h = __float2bfloat16(v);
    l = __float2bfloat16(v - __bfloat162float(h));
}
__device__ __forceinline__ uint32_t pack2bf(__nv_bfloat16 a, __nv_bfloat16 b) {
    return (uint32_t)__bfloat16_as_ushort(a) | ((uint32_t)__bfloat16_as_ushort(b) << 16);
}
// D += A*B  (m16n8k16, bf16 in, f32 acc)
__device__ __forceinline__ void mma16816(float* c, const uint32_t* a, const uint32_t* b) {
    asm volatile(
        "mma.sync.aligned.m16n8k16.row.col.f32.bf16.bf16.f32 "
        "{%0,%1,%2,%3}, {%4,%5,%6,%7}, {%8,%9}, {%0,%1,%2,%3};"
        : "+f"(c[0]), "+f"(c[1]), "+f"(c[2]), "+f"(c[3])
        : "r"(a[0]), "r"(a[1]), "r"(a[2]), "r"(a[3]), "r"(b[0]), "r"(b[1]));
}

// ---------------- mask dtype detector ----------------
__global__ void detect_mask_kernel(const unsigned char* __restrict__ m) {
    __shared__ int has3f, hasodd;
    if (threadIdx.x == 0) { has3f = 0; hasodd = 0; }
    __syncthreads();
    for (int i = threadIdx.x; i < 4096; i += blockDim.x) {
        unsigned char v = m[i];
        if (v == 0x3F) atomicOr(&has3f, 1);
        if (v != 0 && (i & 3)) atomicOr(&hasodd, 1);
    }
    __syncthreads();
    if (threadIdx.x == 0) g_mask_mode = has3f ? 2 : (hasodd ? 1 : 0);
}

// ---------------- weight transpose + bf16 split: src[l][K][N] -> dst[l][nOff+n][K] ----
__global__ void pack_wT_kernel(const float* __restrict__ src,
                               __nv_bfloat16* __restrict__ h, __nv_bfloat16* __restrict__ l,
                               int K, int N, int dstN, int nOff) {
    int idx = blockIdx.x * 256 + threadIdx.x;     // over LL*N*K, k fastest
    if (idx >= LL*N*K) return;
    int k = idx % K;
    int n = (idx / K) % N;
    int ll = idx / (K*N);
    float v = src[((size_t)ll*K + k)*N + n];
    __nv_bfloat16 vh, vl; bsplit(v, vh, vl);
    size_t o = ((size_t)ll*dstN + nOff + n)*K + k;
    h[o] = vh; l[o] = vl;
}

// ---------------- embedding ----------------
__global__ void embed_kernel(const float* __restrict__ x,
                             const float* __restrict__ ea,
                             const void*  __restrict__ mask,
                             const float* __restrict__ nW, const float* __restrict__ nb,
                             const float* __restrict__ eW, const float* __restrict__ eb,
                             const float* __restrict__ noe) {
    int idx = blockIdx.x;                 // b*N*N + i*N + j
    int j = idx & 63;
    int i = (idx >> 6) & 63;
    int b = idx >> 12;
    int d = threadIdx.x;                  // 0..127
    __shared__ float sx[IN_DIM];
    __shared__ float se[EDGE_DIM];
    if (threadIdx.x < IN_DIM)  sx[threadIdx.x] = x[(b*NN + i)*IN_DIM + threadIdx.x];
    if (threadIdx.x < EDGE_DIM) se[threadIdx.x] = ea[((size_t)idx)*EDGE_DIM + threadIdx.x];
    __syncthreads();
    float v;
    if (i == j) {
        v = nb[d];
        #pragma unroll
        for (int e = 0; e < IN_DIM; e++) v = fmaf(sx[e], nW[e*DD + d], v);
    } else {
        bool m;
        int mm = g_mask_mode;
        if (mm == 0)      m = ((const int*)mask)[idx] != 0;
        else if (mm == 1) m = ((const unsigned char*)mask)[idx] != 0;
        else              m = ((const float*)mask)[idx] != 0.f;
        if (m) {
            v = eb[d];
            #pragma unroll
            for (int e = 0; e < EDGE_DIM; e++) v = fmaf(se[e], eW[e*DD + d], v);
        } else {
            v = noe[d];
        }
    }
    g_tok[(size_t)idx*DD + d] = v;
}

// ================= mma.sync bf16 GEMM (split hi/lo, 3-term) =================
// C[M,Nt] = A[M,Kt] @ W  (W pre-transposed/split: BT[Nt][Kt] bf16 hi/lo)
// CTA tile 128x128, 8 warps (4x2), warp tile 32x64, K chunked by 64.
#define BKC 64
#define APAD 72           // smem row stride in bf16 (+8 pad)
#define TILE_ELEMS (128*APAD)
#define MMA_SMEM (4*TILE_ELEMS*2)   // 73728 bytes

__global__ __launch_bounds__(256)
void mma_gemm_kernel(const float* __restrict__ A,
                     const __nv_bfloat16* __restrict__ BTh,
                     const __nv_bfloat16* __restrict__ BTl,
                     const float* __restrict__ bias, const float* __restrict__ res,
                     const float* __restrict__ lng, const float* __restrict__ lnb,
                     float* __restrict__ C, int Kt, int Nt, int relu) {
    extern __shared__ __align__(16) char smem[];
    __nv_bfloat16* Ah = (__nv_bfloat16*)smem;
    __nv_bfloat16* Al = Ah + TILE_ELEMS;
    __nv_bfloat16* Bh = Al + TILE_ELEMS;
    __nv_bfloat16* Bl = Bh + TILE_ELEMS;

    int t   = threadIdx.x;
    int wid = t >> 5, lid = t & 31;
    int g   = lid >> 2, tg = lid & 3;
    int wm0 = (wid >> 1) * 32;           // warp row origin (0..96)
    int wn0 = (wid & 1) * 64;            // warp col origin (0 or 64)
    int bn  = blockIdx.x << 7;
    int bm  = blockIdx.y << 7;

    float acc[2][8][4];
    #pragma unroll
    for (int mt = 0; mt < 2; mt++)
        #pragma unroll
        for (int nt = 0; nt < 8; nt++)
            #pragma unroll
            for (int rr = 0; rr < 4; rr++) acc[mt][nt][rr] = 0.f;

    int lr = t >> 1;                     // 0..127 load row
    int cb = (t & 1) << 5;               // 0 or 32

    for (int k0 = 0; k0 < Kt; k0 += BKC) {
        // ---- A tile: fp32 -> bf16 hi/lo ----
        const float* ap = A + (size_t)(bm + lr)*Kt + k0 + cb;
        __nv_bfloat16* ahp = Ah + lr*APAD + cb;
        __nv_bfloat16* alp = Al + lr*APAD + cb;
        #pragma unroll
        for (int u = 0; u < 8; u++) {
            float4 v = *(const float4*)(ap + u*4);
            __nv_bfloat16 h0,h1,h2,h3,l0,l1,l2,l3;
            bsplit(v.x,h0,l0); bsplit(v.y,h1,l1);
            bsplit(v.z,h2,l2); bsplit(v.w,h3,l3);
            *(uint2*)(ahp + u*4) = make_uint2(pack2bf(h0,h1), pack2bf(h2,h3));
            *(uint2*)(alp + u*4) = make_uint2(pack2bf(l0,l1), pack2bf(l2,l3));
        }
        // ---- B tile: pre-split bf16 copy ----
        const __nv_bfloat16* bhp = BTh + (size_t)(bn + lr)*Kt + k0 + cb;
        const __nv_bfloat16* blp = BTl + (size_t)(bn + lr)*Kt + k0 + cb;
        __nv_bfloat16* dbh = Bh + lr*APAD + cb;
        __nv_bfloat16* dbl = Bl + lr*APAD + cb;
        #pragma unroll
        for (int u = 0; u < 4; u++) {
            *(uint4*)(dbh + u*8) = *(const uint4*)(bhp + u*8);
            *(uint4*)(dbl + u*8) = *(const uint4*)(blp + u*8);
        }
        __syncthreads();
        // ---- MMA over 4 k-steps of 16 ----
        #pragma unroll
        for (int ks = 0; ks < 4; ks++) {
            int kb = ks*16 + tg*2;
            uint32_t ah[2][4], al[2][4];
            #pragma unroll
            for (int mt = 0; mt < 2; mt++) {
                const __nv_bfloat16* pa = Ah + (wm0 + mt*16 + g)*APAD + kb;
                const __nv_bfloat16* pl = Al + (wm0 + mt*16 + g)*APAD + kb;
                ah[mt][0] = *(const uint32_t*)pa;
                ah[mt][1] = *(const uint32_t*)(pa + 8*APAD);
                ah[mt][2] = *(const uint32_t*)(pa + 8);
                ah[mt][3] = *(const uint32_t*)(pa + 8*APAD + 8);
                al[mt][0] = *(const uint32_t*)pl;
                al[mt][1] = *(const uint32_t*)(pl + 8*APAD);
                al[mt][2] = *(const uint32_t*)(pl + 8);
                al[mt][3] = *(const uint32_t*)(pl + 8*APAD + 8);
            }
            #pragma unroll
            for (int nt = 0; nt < 8; nt++) {
                const __nv_bfloat16* pb = Bh + (wn0 + nt*8 + g)*APAD + kb;
                const __nv_bfloat16* ql = Bl + (wn0 + nt*8 + g)*APAD + kb;
                uint32_t bh[2] = { *(const uint32_t*)pb, *(const uint32_t*)(pb + 8) };
                uint32_t bl[2] = { *(const uint32_t*)ql, *(const uint32_t*)(ql + 8) };
                #pragma unroll
                for (int mt = 0; mt < 2; mt++) {
                    mma16816(acc[mt][nt], ah[mt], bh);
                    mma16816(acc[mt][nt], ah[mt], bl);
                    mma16816(acc[mt][nt], al[mt], bh);
                }
            }
        }
        __syncthreads();
    }

    // ---------------- epilogue: bias / residual / relu ----------------
    #pragma unroll
    for (int nt = 0; nt < 8; nt++) {
        int colg = bn + wn0 + nt*8 + tg*2;
        float b0 = 0.f, b1 = 0.f;
        if (bias) { b0 = bias[colg]; b1 = bias[colg+1]; }
        #pragma unroll
        for (int mt = 0; mt < 2; mt++) {
            #pragma unroll
            for (int rp = 0; rp < 2; rp++) {
                int rowg = bm + wm0 + mt*16 + rp*8 + g;
                float v0 = acc[mt][nt][rp*2]   + b0;
                float v1 = acc[mt][nt][rp*2+1] + b1;
                if (res) {
                    float2 rv = *(const float2*)(res + (size_t)rowg*Nt + colg);
                    v0 += rv.x; v1 += rv.y;
                }
                if (relu) { v0 = fmaxf(v0, 0.f); v1 = fmaxf(v1, 0.f); }
                acc[mt][nt][rp*2]   = v0;
                acc[mt][nt][rp*2+1] = v1;
            }
        }
    }

    if (lng) {
        // LN over last dim; only used with Nt==128 (block covers full rows).
        float* rs = (float*)smem;        // [128][2]
        float* rq = rs + 256;            // [128][2]
        #pragma unroll
        for (int mt = 0; mt < 2; mt++) {
            #pragma unroll
            for (int rp = 0; rp < 2; rp++) {
                float s = 0.f, q = 0.f;
                #pragma unroll
                for (int nt = 0; nt < 8; nt++) {
                    float v0 = acc[mt][nt][rp*2], v1 = acc[mt][nt][rp*2+1];
                    s += v0 + v1;
                    q += v0*v0 + v1*v1;
                }
                s += __shfl_xor_sync(0xffffffffu, s, 1);
                s += __shfl_xor_sync(0xffffffffu, s, 2);
                q += __shfl_xor_sync(0xffffffffu, q, 1);
                q += __shfl_xor_sync(0xffffffffu, q, 2);
                if (tg == 0) {
                    int row = wm0 + mt*16 + rp*8 + g;
                    rs[row*2 + (wid & 1)] = s;
                    rq[row*2 + (wid & 1)] = q;
                }
            }
        }
        __syncthreads();
        #pragma unroll
        for (int mt = 0; mt < 2; mt++) {
            #pragma unroll
            for (int rp = 0; rp < 2; rp++) {
                int row = wm0 + mt*16 + rp*8 + g;
                float s = rs[row*2] + rs[row*2+1];
                float q = rq[row*2] + rq[row*2+1];
                float mean = s * 0.0078125f;
                float rstd = rsqrtf(q * 0.0078125f - mean*mean + 1e-5f);
                size_t rowoff = (size_t)(bm + row)*Nt;
                #pragma unroll
                for (int nt = 0; nt < 8; nt++) {
                    int col = wn0 + nt*8 + tg*2;
                    float2 gg = *(const float2*)(lng + col);
                    float2 gb = *(const float2*)(lnb + col);
                    float v0 = (acc[mt][nt][rp*2]   - mean)*rstd*gg.x + gb.x;
                    float v1 = (acc[mt][nt][rp*2+1] - mean)*rstd*gg.y + gb.y;
                    *(float2*)(C + rowoff + bn + col) = make_float2(v0, v1);
                }
            }
        }
    } else {
        #pragma unroll
        for (int mt = 0; mt < 2; mt++) {
            #pragma unroll
            for (int rp = 0; rp < 2; rp++) {
                int rowg = bm + wm0 + mt*16 + rp*8 + g;
                size_t rowoff = (size_t)rowg*Nt;
                #pragma unroll
                for (int nt = 0; nt < 8; nt++) {
                    int colg = bn + wn0 + nt*8 + tg*2;
                    *(float2*)(C + rowoff + colg) =
                        make_float2(acc[mt][nt][rp*2], acc[mt][nt][rp*2+1]);
                }
            }
        }
    }
}

// ---------------- scores: s[b,h,l,i,j] = (1/SCALE) * q[b,i,l,h,:] . k[b,l,j,h,:] ------
__global__ __launch_bounds__(256)
void score_kernel() {
    int bid = blockIdx.x;                  // ((b*H+h)*64 + l)
    int l = bid & 63;
    int h = (bid >> 6) & 3;
    int b = bid >> 8;
    __shared__ float Qs[64][33];
    __shared__ float Ks[64][33];
    int t = threadIdx.x;
    for (int idx = t; idx < 64*32; idx += 256) {
        int r = idx >> 5, c = idx & 31;
        Qs[r][c] = g_qkv[((size_t)((b*NN + r)*NN + l))*512 +       h*DHH + c]; // q, r=i
        Ks[r][c] = g_qkv[((size_t)((b*NN + l)*NN + r))*512 + 128 + h*DHH + c]; // k, r=j
    }
    __syncthreads();
    int tj = t & 15, ti = t >> 4;
    float acc[4][4] = {};
    #pragma unroll
    for (int c = 0; c < 32; c++) {
        float q[4], k[4];
        #pragma unroll
        for (int u = 0; u < 4; u++) { q[u] = Qs[ti*4+u][c]; k[u] = Ks[tj*4+u][c]; }
        #pragma unroll
        for (int i2 = 0; i2 < 4; i2++)
            #pragma unroll
            for (int j2 = 0; j2 < 4; j2++)
                acc[i2][j2] = fmaf(q[i2], k[j2], acc[i2][j2]);
    }
    float* dst = g_s + (size_t)bid * 4096;
    #pragma unroll
    for (int i2 = 0; i2 < 4; i2++)
        #pragma unroll
        for (int j2 = 0; j2 < 4; j2++)
            dst[(ti*4+i2)*64 + tj*4+j2] = acc[i2][j2] * INV_SCALE;
}

// ---------------- softmax over l, in place on g_s[b][h][l][i][j] ----------------
__global__ __launch_bounds__(64)
void softmax_kernel() {
    int bid = blockIdx.x;            // (b*H+h)*64 + i
    int i  = bid & 63;
    int bh = bid >> 6;
    int j  = threadIdx.x;
    size_t base = (size_t)bh * 262144 + (size_t)i*64 + j;
    float v[64];
    float mx = -1e30f;
    #pragma unroll
    for (int l = 0; l < 64; l++) { v[l] = g_s[base + (size_t)l*4096]; mx = fmaxf(mx, v[l]); }
    float s = 0.f;
    #pragma unroll
    for (int l = 0; l < 64; l++) { v[l] = __expf(v[l] - mx); s += v[l]; }
    float inv = 1.f / s;
    #pragma unroll
    for (int l = 0; l < 64; l++) g_s[base + (size_t)l*4096] = v[l] * inv;
}

// ---------------- o[b,i,j,h,d] = sum_l a[b,h,l,i,j]*v1[b,i,l,h,d]*v2[b,l,j,h,d] ------
__global__ __launch_bounds__(256)
void attn_o_kernel() {
    int h = blockIdx.x & 3;
    int i = (blockIdx.x >> 2) & 63;
    int b = blockIdx.x >> 8;
    __shared__ float v1s[64][36];    // [l][dd]
    __shared__ float as[64][64];     // [l][j]
    int t = threadIdx.x;
    for (int idx = t; idx < 64*32; idx += 256) {
        int l = idx >> 5, c = idx & 31;
        v1s[l][c] = g_qkv[((size_t)((b*NN + i)*NN + l))*512 + 256 + h*DHH + c];
    }
    for (int idx = t; idx < 4096; idx += 256) {
        int l = idx >> 6, j = idx & 63;
        as[l][j] = g_s[(size_t)((b*HH + h)*NN + l)*4096 + i*64 + j];
    }
    __syncthreads();
    int td = t & 7;                  // d4 index
    int tj = t >> 3;                 // 0..31
    int j0 = tj, j1 = tj + 32;
    float4 acc0 = {0,0,0,0}, acc1 = {0,0,0,0};
    #pragma unroll 4
    for (int l = 0; l < 64; l++) {
        float a0 = as[l][j0];
        float a1 = as[l][j1];
        float4 v1v = *(const float4*)&v1s[l][td*4];
        const float* base = g_qkv + (size_t)((b*NN + l)*NN)*512 + 384 + h*DHH + td*4;
        float4 w0 = *(const float4*)(base + (size_t)j0*512);
        float4 w1 = *(const float4*)(base + (size_t)j1*512);
        acc0.x = fmaf(a0, v1v.x * w0.x, acc0.x);
        acc0.y = fmaf(a0, v1v.y * w0.y, acc0.y);
        acc0.z = fmaf(a0, v1v.z * w0.z, acc0.z);
        acc0.w = fmaf(a0, v1v.w * w0.w, acc0.w);
        acc1.x = fmaf(a1, v1v.x * w1.x, acc1.x);
        acc1.y = fmaf(a1, v1v.y * w1.y, acc1.y);
        acc1.z = fmaf(a1, v1v.z * w1.z, acc1.z);
        acc1.w = fmaf(a1, v1v.w * w1.w, acc1.w);
    }
    size_t o0 = ((size_t)((b*NN + i)*NN + j0) << 7) + h*DHH + td*4;
    size_t o1 = ((size_t)((b*NN + i)*NN + j1) << 7) + h*DHH + td*4;
    *(float4*)(g_o + o0) = acc0;
    *(float4*)(g_o + o1) = acc1;
}

// ---------------- final: out[b,n] = diag_tok . Wout + bout ----------------
__global__ __launch_bounds__(128)
void out_kernel(const float* __restrict__ Wout, const float* __restrict__ bout,
                float* __restrict__ out) {
    int bn = blockIdx.x;             // b*64 + n
    int n = bn & 63;
    int d = threadIdx.x;
    float v = g_tok[((size_t)bn*NN + n)*DD + d] * Wout[d];
    __shared__ float r[4];
    #pragma unroll
    for (int o = 16; o > 0; o >>= 1) v += __shfl_xor_sync(0xffffffffu, v, o);
    if ((d & 31) == 0) r[d >> 5] = v;
    __syncthreads();
    if (d == 0) out[bn] = r[0] + r[1] + r[2] + r[3] + bout[0];
}

// ---------------- host driver ----------------
extern "C" void kernel_launch(void* const* d_in, const int* in_sizes, int n_in,
                              void* d_out, int out_size) {
    const float* x    = (const float*)d_in[0];
    const float* ea   = (const float*)d_in[1];
    const void*  mask = d_in[2];
    const float* nW   = (const float*)d_in[3];
    const float* nb   = (const float*)d_in[4];
    const float* eW   = (const float*)d_in[5];
    const float* eb   = (const float*)d_in[6];
    const float* noe  = (const float*)d_in[7];
    const float* Wq   = (const float*)d_in[8];
    const float* Wk   = (const float*)d_in[9];
    const float* Wv1  = (const float*)d_in[10];
    const float* Wv2  = (const float*)d_in[11];
    const float* Wo   = (const float*)d_in[12];
    const float* bo   = (const float*)d_in[13];
    const float* ln1g = (const float*)d_in[14];
    const float* ln1b = (const float*)d_in[15];
    const float* W1   = (const float*)d_in[16];
    const float* b1   = (const float*)d_in[17];
    const float* W2   = (const float*)d_in[18];
    const float* b2   = (const float*)d_in[19];
    const float* ln2g = (const float*)d_in[20];
    const float* ln2b = (const float*)d_in[21];
    const float* Wout = (const float*)d_in[22];
    const float* bout = (const float*)d_in[23];

    float *tok, *qkv, *o, *hid;
    __nv_bfloat16 *wqkvh, *wqkvl, *woh, *wol, *w1h, *w1l, *w2h, *w2l;
    cudaGetSymbolAddress((void**)&tok,   g_tok);
    cudaGetSymbolAddress((void**)&qkv,   g_qkv);
    cudaGetSymbolAddress((void**)&o,     g_o);
    cudaGetSymbolAddress((void**)&hid,   g_hid);
    cudaGetSymbolAddress((void**)&wqkvh, g_wqkvT_h);
    cudaGetSymbolAddress((void**)&wqkvl, g_wqkvT_l);
    cudaGetSymbolAddress((void**)&woh,   g_woT_h);
    cudaGetSymbolAddress((void**)&wol,   g_woT_l);
    cudaGetSymbolAddress((void**)&w1h,   g_w1T_h);
    cudaGetSymbolAddress((void**)&w1l,   g_w1T_l);
    cudaGetSymbolAddress((void**)&w2h,   g_w2T_h);
    cudaGetSymbolAddress((void**)&w2l,   g_w2T_l);

    cudaFuncSetAttribute(mma_gemm_kernel,
                         cudaFuncAttributeMaxDynamicSharedMemorySize, MMA_SMEM);

    detect_mask_kernel<<<1, 256>>>((const unsigned char*)mask);
    {
        int nqkv = LL*128*128;  // per source matrix
        pack_wT_kernel<<<(nqkv+255)/256, 256>>>(Wq,  wqkvh, wqkvl, 128, 128, 512, 0);
        pack_wT_kernel<<<(nqkv+255)/256, 256>>>(Wk,  wqkvh, wqkvl, 128, 128, 512, 128);
        pack_wT_kernel<<<(nqkv+255)/256, 256>>>(Wv1, wqkvh, wqkvl, 128, 128, 512, 256);
        pack_wT_kernel<<<(nqkv+255)/256, 256>>>(Wv2, wqkvh, wqkvl, 128, 128, 512, 384);
        pack_wT_kernel<<<(nqkv+255)/256, 256>>>(Wo,  woh,   wol,   128, 128, 128, 0);
        int n1 = LL*128*512;
        pack_wT_kernel<<<(n1+255)/256, 256>>>(W1, w1h, w1l, 128, 512, 512, 0);
        pack_wT_kernel<<<(n1+255)/256, 256>>>(W2, w2h, w2l, 512, 128, 128, 0);
    }
    embed_kernel<<<MROWS, DD>>>(x, ea, mask, nW, nb, eW, eb, noe);

    dim3 gN128(1, MROWS/128);
    dim3 gN512(4, MROWS/128);

    for (int l = 0; l < LL; l++) {
        const __nv_bfloat16* wqh = wqkvh + (size_t)l*512*128;
        const __nv_bfloat16* wql = wqkvl + (size_t)l*512*128;
        const __nv_bfloat16* wo_h = woh + (size_t)l*128*128;
        const __nv_bfloat16* wo_l = wol + (size_t)l*128*128;
        const __nv_bfloat16* w1_h = w1h + (size_t)l*512*128;
        const __nv_bfloat16* w1_l = w1l + (size_t)l*512*128;
        const __nv_bfloat16* w2_h = w2h + (size_t)l*128*512;
        const __nv_bfloat16* w2_l = w2l + (size_t)l*128*512;
        const float* bo_l  = bo  + (size_t)l*DD;
        const float* g1_l  = ln1g + (size_t)l*DD;
        const float* b1l_l = ln1b + (size_t)l*DD;
        const float* bf1_l = b1  + (size_t)l*FF;
        const float* bf2_l = b2  + (size_t)l*DD;
        const float* g2_l  = ln2g + (size_t)l*DD;
        const float* b2l_l = ln2b + (size_t)l*DD;

        // fused QKV projection
        mma_gemm_kernel<<<gN512, 256, MMA_SMEM>>>(tok, wqh, wql,
            nullptr, nullptr, nullptr, nullptr, qkv, 128, 512, 0);

        score_kernel<<<BB*HH*NN, 256>>>();
        softmax_kernel<<<BB*HH*NN, 64>>>();
        attn_o_kernel<<<BB*NN*HH, 256>>>();

        // o-projection + bias + residual + LN1
        mma_gemm_kernel<<<gN128, 256, MMA_SMEM>>>(o, wo_h, wo_l,
            bo_l, tok, g1_l, b1l_l, tok, 128, 128, 0);
        // FFN up + relu
        mma_gemm_kernel<<<gN512, 256, MMA_SMEM>>>(tok, w1_h, w1_l,
            bf1_l, nullptr, nullptr, nullptr, hid, 128, 512, 1);
        // FFN down + bias + residual + LN2
        mma_gemm_kernel<<<gN128, 256, MMA_SMEM>>>(hid, w2_h, w2_l,
            bf2_l, tok, g2_l, b2l_l, tok, 512, 128, 0);
    }

    out_kernel<<<BB*NN, 128>>>(Wout, bout, (float*)d_out);
}

// round 6
// speedup vs baseline: 1.8025x; 1.0607x over previous
#include <cuda_runtime.h>
#include <cuda_bf16.h>
#include <math.h>
#include <stdint.h>

// ---------------- problem constants ----------------
#define BB 8
#define NN 64
#define IN_DIM 16
#define EDGE_DIM 8
#define DD 128
#define HH 4
#define DHH 32
#define LL 3
#define FF 512
#define MROWS (BB*NN*NN)          // 32768
static const float INV_SCALE = 0.17677669529663687f; // 1/sqrt(32)

// ---------------- scratch (device globals; no runtime alloc) ----------------
__device__ float g_tok  [(size_t)MROWS*DD];
__device__ float g_qkv  [(size_t)MROWS*512];          // q|k|v1|v2 packed along N
__device__ float g_o    [(size_t)MROWS*DD];
__device__ float g_hid  [(size_t)MROWS*FF];
__device__ float g_s    [(size_t)BB*HH*NN*NN*NN];     // [b][h][i][l][j]
// transposed + bf16-split weights: layout [l][N][K]
__device__ __nv_bfloat16 g_wqkvT_h[(size_t)LL*512*128];
__device__ __nv_bfloat16 g_wqkvT_l[(size_t)LL*512*128];
__device__ __nv_bfloat16 g_woT_h  [(size_t)LL*128*128];
__device__ __nv_bfloat16 g_woT_l  [(size_t)LL*128*128];
__device__ __nv_bfloat16 g_w1T_h  [(size_t)LL*512*128];
__device__ __nv_bfloat16 g_w1T_l  [(size_t)LL*512*128];
__device__ __nv_bfloat16 g_w2T_h  [(size_t)LL*128*512];
__device__ __nv_bfloat16 g_w2T_l  [(size_t)LL*128*512];
__device__ int g_mask_mode;                            // 0=int32, 1=uint8, 2=float32

// ---------------- helpers ----------------
__device__ __forceinline__ void bsplit(float v, __nv_bfloat16& h, __nv_bfloat16& l) {
    h = __float2bfloat16(v);
    l = __float2bfloat16(v - __bfloat162float(h));
}
__device__ __forceinline__ uint32_t pack2bf(__nv_bfloat16 a, __nv_bfloat16 b) {
    return (uint32_t)__bfloat16_as_ushort(a) | ((uint32_t)__bfloat16_as_ushort(b) << 16);
}
// D += A*B  (m16n8k16, bf16 in, f32 acc)
__device__ __forceinline__ void mma16816(float* c, const uint32_t* a, const uint32_t* b) {
    asm volatile(
        "mma.sync.aligned.m16n8k16.row.col.f32.bf16.bf16.f32 "
        "{%0,%1,%2,%3}, {%4,%5,%6,%7}, {%8,%9}, {%0,%1,%2,%3};"
        : "+f"(c[0]), "+f"(c[1]), "+f"(c[2]), "+f"(c[3])
        : "r"(a[0]), "r"(a[1]), "r"(a[2]), "r"(a[3]), "r"(b[0]), "r"(b[1]));
}

// ---------------- mask dtype detector ----------------
__global__ void detect_mask_kernel(const unsigned char* __restrict__ m) {
    __shared__ int has3f, hasodd;
    if (threadIdx.x == 0) { has3f = 0; hasodd = 0; }
    __syncthreads();
    for (int i = threadIdx.x; i < 4096; i += blockDim.x) {
        unsigned char v = m[i];
        if (v == 0x3F) atomicOr(&has3f, 1);
        if (v != 0 && (i & 3)) atomicOr(&hasodd, 1);
    }
    __syncthreads();
    if (threadIdx.x == 0) g_mask_mode = has3f ? 2 : (hasodd ? 1 : 0);
}

// ---------------- merged weight transpose + bf16 split ----------------
// src[l][K][N] -> dst[l][nOff+n][K], hi/lo bf16
// segments (blocks): Wq[0,192) Wk[192,384) Wv1[384,576) Wv2[576,768)
//                    Wo[768,960) W1[960,1728) W2[1728,2496)
__global__ void pack_all_kernel(const float* __restrict__ Wq, const float* __restrict__ Wk,
                                const float* __restrict__ Wv1, const float* __restrict__ Wv2,
                                const float* __restrict__ Wo, const float* __restrict__ W1,
                                const float* __restrict__ W2,
                                __nv_bfloat16* __restrict__ qh, __nv_bfloat16* __restrict__ ql,
                                __nv_bfloat16* __restrict__ oh, __nv_bfloat16* __restrict__ ol,
                                __nv_bfloat16* __restrict__ h1, __nv_bfloat16* __restrict__ l1,
                                __nv_bfloat16* __restrict__ h2, __nv_bfloat16* __restrict__ l2) {
    int blk = blockIdx.x;
    const float* src; __nv_bfloat16 *dh, *dl;
    int K, N, dstN, nOff, idx;
    if (blk < 768) {
        int seg = blk / 192;
        idx = (blk - seg*192)*256 + threadIdx.x;
        src = (seg==0)?Wq:(seg==1)?Wk:(seg==2)?Wv1:Wv2;
        dh = qh; dl = ql; K = 128; N = 128; dstN = 512; nOff = seg*128;
    } else if (blk < 960) {
        idx = (blk-768)*256 + threadIdx.x;
        src = Wo; dh = oh; dl = ol; K = 128; N = 128; dstN = 128; nOff = 0;
    } else if (blk < 1728) {
        idx = (blk-960)*256 + threadIdx.x;
        src = W1; dh = h1; dl = l1; K = 128; N = 512; dstN = 512; nOff = 0;
    } else {
        idx = (blk-1728)*256 + threadIdx.x;
        src = W2; dh = h2; dl = l2; K = 512; N = 128; dstN = 128; nOff = 0;
    }
    if (idx >= LL*N*K) return;
    int k = idx % K;
    int n = (idx / K) % N;
    int ll = idx / (K*N);
    float v = src[((size_t)ll*K + k)*N + n];
    __nv_bfloat16 vh, vl; bsplit(v, vh, vl);
    size_t o = ((size_t)ll*dstN + nOff + n)*K + k;
    dh[o] = vh; dl[o] = vl;
}

// ---------------- embedding ----------------
__global__ void embed_kernel(const float* __restrict__ x,
                             const float* __restrict__ ea,
                             const void*  __restrict__ mask,
                             const float* __restrict__ nW, const float* __restrict__ nb,
                             const float* __restrict__ eW, const float* __restrict__ eb,
                             const float* __restrict__ noe) {
    int idx = blockIdx.x;                 // b*N*N + i*N + j
    int j = idx & 63;
    int i = (idx >> 6) & 63;
    int b = idx >> 12;
    int d = threadIdx.x;                  // 0..127
    __shared__ float sx[IN_DIM];
    __shared__ float se[EDGE_DIM];
    if (threadIdx.x < IN_DIM)  sx[threadIdx.x] = x[(b*NN + i)*IN_DIM + threadIdx.x];
    if (threadIdx.x < EDGE_DIM) se[threadIdx.x] = ea[((size_t)idx)*EDGE_DIM + threadIdx.x];
    __syncthreads();
    float v;
    if (i == j) {
        v = nb[d];
        #pragma unroll
        for (int e = 0; e < IN_DIM; e++) v = fmaf(sx[e], nW[e*DD + d], v);
    } else {
        bool m;
        int mm = g_mask_mode;
        if (mm == 0)      m = ((const int*)mask)[idx] != 0;
        else if (mm == 1) m = ((const unsigned char*)mask)[idx] != 0;
        else              m = ((const float*)mask)[idx] != 0.f;
        if (m) {
            v = eb[d];
            #pragma unroll
            for (int e = 0; e < EDGE_DIM; e++) v = fmaf(se[e], eW[e*DD + d], v);
        } else {
            v = noe[d];
        }
    }
    g_tok[(size_t)idx*DD + d] = v;
}

// ================= mma.sync bf16 GEMM (split hi/lo, 3-term) =================
#define BKC 64
#define APAD 72           // smem row stride in bf16 (+8 pad)
#define TILE_ELEMS (128*APAD)
#define MMA_SMEM (4*TILE_ELEMS*2)   // 73728 bytes

__global__ __launch_bounds__(256)
void mma_gemm_kernel(const float* __restrict__ A,
                     const __nv_bfloat16* __restrict__ BTh,
                     const __nv_bfloat16* __restrict__ BTl,
                     const float* __restrict__ bias, const float* __restrict__ res,
                     const float* __restrict__ lng, const float* __restrict__ lnb,
                     float* __restrict__ C, int Kt, int Nt, int relu) {
    extern __shared__ __align__(16) char smem[];
    __nv_bfloat16* Ah = (__nv_bfloat16*)smem;
    __nv_bfloat16* Al = Ah + TILE_ELEMS;
    __nv_bfloat16* Bh = Al + TILE_ELEMS;
    __nv_bfloat16* Bl = Bh + TILE_ELEMS;

    int t   = threadIdx.x;
    int wid = t >> 5, lid = t & 31;
    int g   = lid >> 2, tg = lid & 3;
    int wm0 = (wid >> 1) * 32;
    int wn0 = (wid & 1) * 64;
    int bn  = blockIdx.x << 7;
    int bm  = blockIdx.y << 7;

    float acc[2][8][4];
    #pragma unroll
    for (int mt = 0; mt < 2; mt++)
        #pragma unroll
        for (int nt = 0; nt < 8; nt++)
            #pragma unroll
            for (int rr = 0; rr < 4; rr++) acc[mt][nt][rr] = 0.f;

    int lr = t >> 1;
    int cb = (t & 1) << 5;

    for (int k0 = 0; k0 < Kt; k0 += BKC) {
        const float* ap = A + (size_t)(bm + lr)*Kt + k0 + cb;
        __nv_bfloat16* ahp = Ah + lr*APAD + cb;
        __nv_bfloat16* alp = Al + lr*APAD + cb;
        #pragma unroll
        for (int u = 0; u < 8; u++) {
            float4 v = *(const float4*)(ap + u*4);
            __nv_bfloat16 h0,h1,h2,h3,l0,l1,l2,l3;
            bsplit(v.x,h0,l0); bsplit(v.y,h1,l1);
            bsplit(v.z,h2,l2); bsplit(v.w,h3,l3);
            *(uint2*)(ahp + u*4) = make_uint2(pack2bf(h0,h1), pack2bf(h2,h3));
            *(uint2*)(alp + u*4) = make_uint2(pack2bf(l0,l1), pack2bf(l2,l3));
        }
        const __nv_bfloat16* bhp = BTh + (size_t)(bn + lr)*Kt + k0 + cb;
        const __nv_bfloat16* blp = BTl + (size_t)(bn + lr)*Kt + k0 + cb;
        __nv_bfloat16* dbh = Bh + lr*APAD + cb;
        __nv_bfloat16* dbl = Bl + lr*APAD + cb;
        #pragma unroll
        for (int u = 0; u < 4; u++) {
            *(uint4*)(dbh + u*8) = *(const uint4*)(bhp + u*8);
            *(uint4*)(dbl + u*8) = *(const uint4*)(blp + u*8);
        }
        __syncthreads();
        #pragma unroll
        for (int ks = 0; ks < 4; ks++) {
            int kb = ks*16 + tg*2;
            uint32_t ah[2][4], al[2][4];
            #pragma unroll
            for (int mt = 0; mt < 2; mt++) {
                const __nv_bfloat16* pa = Ah + (wm0 + mt*16 + g)*APAD + kb;
                const __nv_bfloat16* pl = Al + (wm0 + mt*16 + g)*APAD + kb;
                ah[mt][0] = *(const uint32_t*)pa;
                ah[mt][1] = *(const uint32_t*)(pa + 8*APAD);
                ah[mt][2] = *(const uint32_t*)(pa + 8);
                ah[mt][3] = *(const uint32_t*)(pa + 8*APAD + 8);
                al[mt][0] = *(const uint32_t*)pl;
                al[mt][1] = *(const uint32_t*)(pl + 8*APAD);
                al[mt][2] = *(const uint32_t*)(pl + 8);
                al[mt][3] = *(const uint32_t*)(pl + 8*APAD + 8);
            }
            #pragma unroll
            for (int nt = 0; nt < 8; nt++) {
                const __nv_bfloat16* pb = Bh + (wn0 + nt*8 + g)*APAD + kb;
                const __nv_bfloat16* ql = Bl + (wn0 + nt*8 + g)*APAD + kb;
                uint32_t bh[2] = { *(const uint32_t*)pb, *(const uint32_t*)(pb + 8) };
                uint32_t bl[2] = { *(const uint32_t*)ql, *(const uint32_t*)(ql + 8) };
                #pragma unroll
                for (int mt = 0; mt < 2; mt++) {
                    mma16816(acc[mt][nt], ah[mt], bh);
                    mma16816(acc[mt][nt], ah[mt], bl);
                    mma16816(acc[mt][nt], al[mt], bh);
                }
            }
        }
        __syncthreads();
    }

    // ---------------- epilogue: bias / residual / relu ----------------
    #pragma unroll
    for (int nt = 0; nt < 8; nt++) {
        int colg = bn + wn0 + nt*8 + tg*2;
        float b0 = 0.f, b1 = 0.f;
        if (bias) { b0 = bias[colg]; b1 = bias[colg+1]; }
        #pragma unroll
        for (int mt = 0; mt < 2; mt++) {
            #pragma unroll
            for (int rp = 0; rp < 2; rp++) {
                int rowg = bm + wm0 + mt*16 + rp*8 + g;
                float v0 = acc[mt][nt][rp*2]   + b0;
                float v1 = acc[mt][nt][rp*2+1] + b1;
                if (res) {
                    float2 rv = *(const float2*)(res + (size_t)rowg*Nt + colg);
                    v0 += rv.x; v1 += rv.y;
                }
                if (relu) { v0 = fmaxf(v0, 0.f); v1 = fmaxf(v1, 0.f); }
                acc[mt][nt][rp*2]   = v0;
                acc[mt][nt][rp*2+1] = v1;
            }
        }
    }

    if (lng) {
        float* rs = (float*)smem;        // [128][2]
        float* rq = rs + 256;            // [128][2]
        #pragma unroll
        for (int mt = 0; mt < 2; mt++) {
            #pragma unroll
            for (int rp = 0; rp < 2; rp++) {
                float s = 0.f, q = 0.f;
                #pragma unroll
                for (int nt = 0; nt < 8; nt++) {
                    float v0 = acc[mt][nt][rp*2], v1 = acc[mt][nt][rp*2+1];
                    s += v0 + v1;
                    q += v0*v0 + v1*v1;
                }
                s += __shfl_xor_sync(0xffffffffu, s, 1);
                s += __shfl_xor_sync(0xffffffffu, s, 2);
                q += __shfl_xor_sync(0xffffffffu, q, 1);
                q += __shfl_xor_sync(0xffffffffu, q, 2);
                if (tg == 0) {
                    int row = wm0 + mt*16 + rp*8 + g;
                    rs[row*2 + (wid & 1)] = s;
                    rq[row*2 + (wid & 1)] = q;
                }
            }
        }
        __syncthreads();
        #pragma unroll
        for (int mt = 0; mt < 2; mt++) {
            #pragma unroll
            for (int rp = 0; rp < 2; rp++) {
                int row = wm0 + mt*16 + rp*8 + g;
                float s = rs[row*2] + rs[row*2+1];
                float q = rq[row*2] + rq[row*2+1];
                float mean = s * 0.0078125f;
                float rstd = rsqrtf(q * 0.0078125f - mean*mean + 1e-5f);
                size_t rowoff = (size_t)(bm + row)*Nt;
                #pragma unroll
                for (int nt = 0; nt < 8; nt++) {
                    int col = wn0 + nt*8 + tg*2;
                    float2 gg = *(const float2*)(lng + col);
                    float2 gb = *(const float2*)(lnb + col);
                    float v0 = (acc[mt][nt][rp*2]   - mean)*rstd*gg.x + gb.x;
                    float v1 = (acc[mt][nt][rp*2+1] - mean)*rstd*gg.y + gb.y;
                    *(float2*)(C + rowoff + bn + col) = make_float2(v0, v1);
                }
            }
        }
    } else {
        #pragma unroll
        for (int mt = 0; mt < 2; mt++) {
            #pragma unroll
            for (int rp = 0; rp < 2; rp++) {
                int rowg = bm + wm0 + mt*16 + rp*8 + g;
                size_t rowoff = (size_t)rowg*Nt;
                #pragma unroll
                for (int nt = 0; nt < 8; nt++) {
                    int colg = bn + wn0 + nt*8 + tg*2;
                    *(float2*)(C + rowoff + colg) =
                        make_float2(acc[mt][nt][rp*2], acc[mt][nt][rp*2+1]);
                }
            }
        }
    }
}

// ---------------- scores: s[b,h,i,l,j] = (1/SCALE) * q[b,i,l,h,:] . k[b,l,j,h,:] ------
__global__ __launch_bounds__(256)
void score_kernel() {
    int bid = blockIdx.x;                  // bh*64 + l
    int l  = bid & 63;
    int bh = bid >> 6;
    int h  = bh & 3;
    int b  = bh >> 2;
    __shared__ float Qs[64][33];
    __shared__ float Ks[64][33];
    int t = threadIdx.x;
    for (int idx = t; idx < 64*32; idx += 256) {
        int r = idx >> 5, c = idx & 31;
        Qs[r][c] = g_qkv[((size_t)((b*NN + r)*NN + l))*512 +       h*DHH + c]; // q, r=i
        Ks[r][c] = g_qkv[((size_t)((b*NN + l)*NN + r))*512 + 128 + h*DHH + c]; // k, r=j
    }
    __syncthreads();
    int tj = t & 15, ti = t >> 4;
    float acc[4][4] = {};
    #pragma unroll
    for (int c = 0; c < 32; c++) {
        float q[4], k[4];
        #pragma unroll
        for (int u = 0; u < 4; u++) { q[u] = Qs[ti*4+u][c]; k[u] = Ks[tj*4+u][c]; }
        #pragma unroll
        for (int i2 = 0; i2 < 4; i2++)
            #pragma unroll
            for (int j2 = 0; j2 < 4; j2++)
                acc[i2][j2] = fmaf(q[i2], k[j2], acc[i2][j2]);
    }
    // write s[b][h][i][l][j]
    #pragma unroll
    for (int i2 = 0; i2 < 4; i2++) {
        int i = ti*4 + i2;
        float4 v = make_float4(acc[i2][0]*INV_SCALE, acc[i2][1]*INV_SCALE,
                               acc[i2][2]*INV_SCALE, acc[i2][3]*INV_SCALE);
        *(float4*)(g_s + ((size_t)(bh*NN + i)*NN + l)*NN + tj*4) = v;
    }
}

// ---------------- softmax over l on s[b][h][i][l][j] (contiguous tile) ------------
__global__ __launch_bounds__(256)
void softmax_kernel() {
    int bid = blockIdx.x;            // bh*64 + i
    size_t base = (size_t)bid * 4096;
    int t = threadIdx.x;
    int j = t & 63, lq = t >> 6;     // 4 l-groups of 16
    __shared__ float pm[4][64], ps[4][64];
    float v[16];
    float mx = -1e30f;
    #pragma unroll
    for (int u = 0; u < 16; u++) {
        v[u] = g_s[base + (size_t)(lq*16 + u)*64 + j];
        mx = fmaxf(mx, v[u]);
    }
    pm[lq][j] = mx;
    __syncthreads();
    mx = fmaxf(fmaxf(pm[0][j], pm[1][j]), fmaxf(pm[2][j], pm[3][j]));
    float s = 0.f;
    #pragma unroll
    for (int u = 0; u < 16; u++) { v[u] = __expf(v[u] - mx); s += v[u]; }
    ps[lq][j] = s;
    __syncthreads();
    float inv = 1.f / (ps[0][j] + ps[1][j] + ps[2][j] + ps[3][j]);
    #pragma unroll
    for (int u = 0; u < 16; u++)
        g_s[base + (size_t)(lq*16 + u)*64 + j] = v[u] * inv;
}

// ---------------- tiled attn_o: o[b,i,j,h,d] = sum_l a[b,h,i,l,j]*v1[b,i,l,h,d]*v2[b,l,j,h,d]
// block = (b, h, i-tile 16, j-tile 16); l chunked by 16.  smem ~88KB (dynamic).
#define AT_V1 0                         // [i][l][36] floats
#define AT_V2 (16*16*36)                // [l][j][36]
#define AT_A  (2*16*16*36)              // [l][i][16]
#define ATTN_SMEM ((2*16*16*36 + 16*16*16)*4)

__global__ __launch_bounds__(256)
void attn_o_kernel() {
    extern __shared__ __align__(16) float sm[];
    float* v1s = sm + AT_V1;
    float* v2s = sm + AT_V2;
    float* as_ = sm + AT_A;
    int bx = blockIdx.x;
    int jt = bx & 3;
    int it = (bx >> 2) & 3;
    int h  = (bx >> 4) & 3;
    int b  = bx >> 6;
    int bh = b*HH + h;
    int i0 = it*16, j0 = jt*16;
    int t = threadIdx.x;
    int ti = t >> 4, tj = t & 15;

    float acc[32];
    #pragma unroll
    for (int d = 0; d < 32; d++) acc[d] = 0.f;

    for (int lc = 0; lc < 4; lc++) {
        int l0 = lc*16;
        // v1 [i][l][d]: 2048 float4
        #pragma unroll
        for (int k = 0; k < 8; k++) {
            int fid = t + k*256;
            int dq = fid & 7, l = (fid >> 3) & 15, i_ = fid >> 7;
            float4 v = *(const float4*)(g_qkv +
                ((size_t)((b*NN + i0 + i_)*NN + l0 + l))*512 + 256 + h*DHH + dq*4);
            *(float4*)(v1s + (i_*16 + l)*36 + dq*4) = v;
        }
        // v2 [l][j][d]: 2048 float4
        #pragma unroll
        for (int k = 0; k < 8; k++) {
            int fid = t + k*256;
            int dq = fid & 7, j_ = (fid >> 3) & 15, l_ = fid >> 7;
            float4 v = *(const float4*)(g_qkv +
                ((size_t)((b*NN + l0 + l_)*NN + j0 + j_))*512 + 384 + h*DHH + dq*4);
            *(float4*)(v2s + (l_*16 + j_)*36 + dq*4) = v;
        }
        // a [l][i][j]: 1024 float4
        #pragma unroll
        for (int k = 0; k < 4; k++) {
            int fid = t + k*256;
            int jq = fid & 3, i_ = (fid >> 2) & 15, l_ = fid >> 6;
            float4 v = *(const float4*)(g_s +
                ((size_t)(bh*NN + i0 + i_)*NN + l0 + l_)*NN + j0 + jq*4);
            *(float4*)(as_ + (l_*16 + i_)*16 + jq*4) = v;
        }
        __syncthreads();
        #pragma unroll 4
        for (int l = 0; l < 16; l++) {
            float a = as_[(l*16 + ti)*16 + tj];
            const float* p1 = v1s + (ti*16 + l)*36;
            const float* p2 = v2s + (l*16 + tj)*36;
            #pragma unroll
            for (int dq = 0; dq < 8; dq++) {
                float4 x = *(const float4*)(p1 + dq*4);
                float4 y = *(const float4*)(p2 + dq*4);
                acc[dq*4+0] = fmaf(a, x.x * y.x, acc[dq*4+0]);
                acc[dq*4+1] = fmaf(a, x.y * y.y, acc[dq*4+1]);
                acc[dq*4+2] = fmaf(a, x.z * y.z, acc[dq*4+2]);
                acc[dq*4+3] = fmaf(a, x.w * y.w, acc[dq*4+3]);
            }
        }
        __syncthreads();
    }
    // write o[b, i0+ti, j0+tj, h, :]
    float* op = g_o + ((size_t)((b*NN + i0 + ti)*NN + j0 + tj) << 7) + h*DHH;
    #pragma unroll
    for (int dq = 0; dq < 8; dq++)
        *(float4*)(op + dq*4) = make_float4(acc[dq*4], acc[dq*4+1], acc[dq*4+2], acc[dq*4+3]);
}

// ---------------- final: out[b,n] = diag_tok . Wout + bout ----------------
__global__ __launch_bounds__(128)
void out_kernel(const float* __restrict__ Wout, const float* __restrict__ bout,
                float* __restrict__ out) {
    int bn = blockIdx.x;             // b*64 + n
    int n = bn & 63;
    int d = threadIdx.x;
    float v = g_tok[((size_t)bn*NN + n)*DD + d] * Wout[d];
    __shared__ float r[4];
    #pragma unroll
    for (int o = 16; o > 0; o >>= 1) v += __shfl_xor_sync(0xffffffffu, v, o);
    if ((d & 31) == 0) r[d >> 5] = v;
    __syncthreads();
    if (d == 0) out[bn] = r[0] + r[1] + r[2] + r[3] + bout[0];
}

// ---------------- host driver ----------------
extern "C" void kernel_launch(void* const* d_in, const int* in_sizes, int n_in,
                              void* d_out, int out_size) {
    const float* x    = (const float*)d_in[0];
    const float* ea   = (const float*)d_in[1];
    const void*  mask = d_in[2];
    const float* nW   = (const float*)d_in[3];
    const float* nb   = (const float*)d_in[4];
    const float* eW   = (const float*)d_in[5];
    const float* eb   = (const float*)d_in[6];
    const float* noe  = (const float*)d_in[7];
    const float* Wq   = (const float*)d_in[8];
    const float* Wk   = (const float*)d_in[9];
    const float* Wv1  = (const float*)d_in[10];
    const float* Wv2  = (const float*)d_in[11];
    const float* Wo   = (const float*)d_in[12];
    const float* bo   = (const float*)d_in[13];
    const float* ln1g = (const float*)d_in[14];
    const float* ln1b = (const float*)d_in[15];
    const float* W1   = (const float*)d_in[16];
    const float* b1   = (const float*)d_in[17];
    const float* W2   = (const float*)d_in[18];
    const float* b2   = (const float*)d_in[19];
    const float* ln2g = (const float*)d_in[20];
    const float* ln2b = (const float*)d_in[21];
    const float* Wout = (const float*)d_in[22];
    const float* bout = (const float*)d_in[23];

    float *tok, *qkv, *o, *hid;
    __nv_bfloat16 *wqkvh, *wqkvl, *woh, *wol, *w1h, *w1l, *w2h, *w2l;
    cudaGetSymbolAddress((void**)&tok,   g_tok);
    cudaGetSymbolAddress((void**)&qkv,   g_qkv);
    cudaGetSymbolAddress((void**)&o,     g_o);
    cudaGetSymbolAddress((void**)&hid,   g_hid);
    cudaGetSymbolAddress((void**)&wqkvh, g_wqkvT_h);
    cudaGetSymbolAddress((void**)&wqkvl, g_wqkvT_l);
    cudaGetSymbolAddress((void**)&woh,   g_woT_h);
    cudaGetSymbolAddress((void**)&wol,   g_woT_l);
    cudaGetSymbolAddress((void**)&w1h,   g_w1T_h);
    cudaGetSymbolAddress((void**)&w1l,   g_w1T_l);
    cudaGetSymbolAddress((void**)&w2h,   g_w2T_h);
    cudaGetSymbolAddress((void**)&w2l,   g_w2T_l);

    cudaFuncSetAttribute(mma_gemm_kernel,
                         cudaFuncAttributeMaxDynamicSharedMemorySize, MMA_SMEM);
    cudaFuncSetAttribute(attn_o_kernel,
                         cudaFuncAttributeMaxDynamicSharedMemorySize, ATTN_SMEM);

    detect_mask_kernel<<<1, 256>>>((const unsigned char*)mask);
    pack_all_kernel<<<2496, 256>>>(Wq, Wk, Wv1, Wv2, Wo, W1, W2,
                                   wqkvh, wqkvl, woh, wol, w1h, w1l, w2h, w2l);
    embed_kernel<<<MROWS, DD>>>(x, ea, mask, nW, nb, eW, eb, noe);

    dim3 gN128(1, MROWS/128);
    dim3 gN512(4, MROWS/128);

    for (int l = 0; l < LL; l++) {
        const __nv_bfloat16* wqh = wqkvh + (size_t)l*512*128;
        const __nv_bfloat16* wql = wqkvl + (size_t)l*512*128;
        const __nv_bfloat16* wo_h = woh + (size_t)l*128*128;
        const __nv_bfloat16* wo_l = wol + (size_t)l*128*128;
        const __nv_bfloat16* w1_h = w1h + (size_t)l*512*128;
        const __nv_bfloat16* w1_l = w1l + (size_t)l*512*128;
        const __nv_bfloat16* w2_h = w2h + (size_t)l*128*512;
        const __nv_bfloat16* w2_l = w2l + (size_t)l*128*512;
        const float* bo_l  = bo  + (size_t)l*DD;
        const float* g1_l  = ln1g + (size_t)l*DD;
        const float* b1l_l = ln1b + (size_t)l*DD;
        const float* bf1_l = b1  + (size_t)l*FF;
        const float* bf2_l = b2  + (size_t)l*DD;
        const float* g2_l  = ln2g + (size_t)l*DD;
        const float* b2l_l = ln2b + (size_t)l*DD;

        // fused QKV projection
        mma_gemm_kernel<<<gN512, 256, MMA_SMEM>>>(tok, wqh, wql,
            nullptr, nullptr, nullptr, nullptr, qkv, 128, 512, 0);

        score_kernel<<<BB*HH*NN, 256>>>();
        softmax_kernel<<<BB*HH*NN, 256>>>();
        attn_o_kernel<<<512, 256, ATTN_SMEM>>>();

        // o-projection + bias + residual + LN1
        mma_gemm_kernel<<<gN128, 256, MMA_SMEM>>>(o, wo_h, wo_l,
            bo_l, tok, g1_l, b1l_l, tok, 128, 128, 0);
        // FFN up + relu
        mma_gemm_kernel<<<gN512, 256, MMA_SMEM>>>(tok, w1_h, w1_l,
            bf1_l, nullptr, nullptr, nullptr, hid, 128, 512, 1);
        // FFN down + bias + residual + LN2
        mma_gemm_kernel<<<gN128, 256, MMA_SMEM>>>(hid, w2_h, w2_l,
            bf2_l, tok, g2_l, b2l_l, tok, 512, 128, 0);
    }

    out_kernel<<<BB*NN, 128>>>(Wout, bout, (float*)d_out);
}

// round 7
// speedup vs baseline: 1.9048x; 1.0567x over previous
#include <cuda_runtime.h>
#include <cuda_bf16.h>
#include <math.h>
#include <stdint.h>

// ---------------- problem constants ----------------
#define BB 8
#define NN 64
#define IN_DIM 16
#define EDGE_DIM 8
#define DD 128
#define HH 4
#define DHH 32
#define LL 3
#define FF 512
#define MROWS (BB*NN*NN)          // 32768
static const float INV_SCALE = 0.17677669529663687f; // 1/sqrt(32)

// ---------------- scratch (device globals; no runtime alloc) ----------------
__device__ float g_tok  [(size_t)MROWS*DD];
__device__ float g_qkv  [(size_t)MROWS*512];          // q|k|v1|v2 packed along N
__device__ float g_o    [(size_t)MROWS*DD];
__device__ float g_hid  [(size_t)MROWS*FF];
__device__ float g_s    [(size_t)BB*HH*NN*NN*NN];     // [b][h][i][l][j]
// transposed + bf16-split weights: layout [l][N][K]
__device__ __nv_bfloat16 g_wqkvT_h[(size_t)LL*512*128];
__device__ __nv_bfloat16 g_wqkvT_l[(size_t)LL*512*128];
__device__ __nv_bfloat16 g_woT_h  [(size_t)LL*128*128];
__device__ __nv_bfloat16 g_woT_l  [(size_t)LL*128*128];
__device__ __nv_bfloat16 g_w1T_h  [(size_t)LL*512*128];
__device__ __nv_bfloat16 g_w1T_l  [(size_t)LL*512*128];
__device__ __nv_bfloat16 g_w2T_h  [(size_t)LL*128*512];
__device__ __nv_bfloat16 g_w2T_l  [(size_t)LL*128*512];
__device__ int g_mask_mode;                            // 0=int32, 1=uint8, 2=float32

// ---------------- helpers ----------------
__device__ __forceinline__ void bsplit(float v, __nv_bfloat16& h, __nv_bfloat16& l) {
    h = __float2bfloat16(v);
    l = __float2bfloat16(v - __bfloat162float(h));
}
__device__ __forceinline__ uint32_t pack2bf(__nv_bfloat16 a, __nv_bfloat16 b) {
    return (uint32_t)__bfloat16_as_ushort(a) | ((uint32_t)__bfloat16_as_ushort(b) << 16);
}
__device__ __forceinline__ uint32_t smem_u32(const void* p) {
    uint32_t a;
    asm("{ .reg .u64 t; cvta.to.shared.u64 t, %1; cvt.u32.u64 %0, t; }" : "=r"(a) : "l"(p));
    return a;
}
// D += A*B  (m16n8k16, bf16 in, f32 acc)
__device__ __forceinline__ void mma16816(float* c, const uint32_t* a, const uint32_t* b) {
    asm volatile(
        "mma.sync.aligned.m16n8k16.row.col.f32.bf16.bf16.f32 "
        "{%0,%1,%2,%3}, {%4,%5,%6,%7}, {%8,%9}, {%0,%1,%2,%3};"
        : "+f"(c[0]), "+f"(c[1]), "+f"(c[2]), "+f"(c[3])
        : "r"(a[0]), "r"(a[1]), "r"(a[2]), "r"(a[3]), "r"(b[0]), "r"(b[1]));
}
__device__ __forceinline__ void ldsm4(uint32_t addr, uint32_t* r) {
    asm volatile("ldmatrix.sync.aligned.m8n8.x4.shared.b16 {%0,%1,%2,%3}, [%4];"
        : "=r"(r[0]), "=r"(r[1]), "=r"(r[2]), "=r"(r[3]) : "r"(addr));
}

// ---------------- mask dtype detector ----------------
__global__ void detect_mask_kernel(const unsigned char* __restrict__ m) {
    __shared__ int has3f, hasodd;
    if (threadIdx.x == 0) { has3f = 0; hasodd = 0; }
    __syncthreads();
    for (int i = threadIdx.x; i < 4096; i += blockDim.x) {
        unsigned char v = m[i];
        if (v == 0x3F) atomicOr(&has3f, 1);
        if (v != 0 && (i & 3)) atomicOr(&hasodd, 1);
    }
    __syncthreads();
    if (threadIdx.x == 0) g_mask_mode = has3f ? 2 : (hasodd ? 1 : 0);
}

// ---------------- merged weight transpose + bf16 split ----------------
__global__ void pack_all_kernel(const float* __restrict__ Wq, const float* __restrict__ Wk,
                                const float* __restrict__ Wv1, const float* __restrict__ Wv2,
                                const float* __restrict__ Wo, const float* __restrict__ W1,
                                const float* __restrict__ W2,
                                __nv_bfloat16* __restrict__ qh, __nv_bfloat16* __restrict__ ql,
                                __nv_bfloat16* __restrict__ oh, __nv_bfloat16* __restrict__ ol,
                                __nv_bfloat16* __restrict__ h1, __nv_bfloat16* __restrict__ l1,
                                __nv_bfloat16* __restrict__ h2, __nv_bfloat16* __restrict__ l2) {
    int blk = blockIdx.x;
    const float* src; __nv_bfloat16 *dh, *dl;
    int K, N, dstN, nOff, idx;
    if (blk < 768) {
        int seg = blk / 192;
        idx = (blk - seg*192)*256 + threadIdx.x;
        src = (seg==0)?Wq:(seg==1)?Wk:(seg==2)?Wv1:Wv2;
        dh = qh; dl = ql; K = 128; N = 128; dstN = 512; nOff = seg*128;
    } else if (blk < 960) {
        idx = (blk-768)*256 + threadIdx.x;
        src = Wo; dh = oh; dl = ol; K = 128; N = 128; dstN = 128; nOff = 0;
    } else if (blk < 1728) {
        idx = (blk-960)*256 + threadIdx.x;
        src = W1; dh = h1; dl = l1; K = 128; N = 512; dstN = 512; nOff = 0;
    } else {
        idx = (blk-1728)*256 + threadIdx.x;
        src = W2; dh = h2; dl = l2; K = 512; N = 128; dstN = 128; nOff = 0;
    }
    if (idx >= LL*N*K) return;
    int k = idx % K;
    int n = (idx / K) % N;
    int ll = idx / (K*N);
    float v = src[((size_t)ll*K + k)*N + n];
    __nv_bfloat16 vh, vl; bsplit(v, vh, vl);
    size_t o = ((size_t)ll*dstN + nOff + n)*K + k;
    dh[o] = vh; dl[o] = vl;
}

// ---------------- embedding ----------------
__global__ void embed_kernel(const float* __restrict__ x,
                             const float* __restrict__ ea,
                             const void*  __restrict__ mask,
                             const float* __restrict__ nW, const float* __restrict__ nb,
                             const float* __restrict__ eW, const float* __restrict__ eb,
                             const float* __restrict__ noe) {
    int idx = blockIdx.x;                 // b*N*N + i*N + j
    int j = idx & 63;
    int i = (idx >> 6) & 63;
    int b = idx >> 12;
    int d = threadIdx.x;                  // 0..127
    __shared__ float sx[IN_DIM];
    __shared__ float se[EDGE_DIM];
    if (threadIdx.x < IN_DIM)  sx[threadIdx.x] = x[(b*NN + i)*IN_DIM + threadIdx.x];
    if (threadIdx.x < EDGE_DIM) se[threadIdx.x] = ea[((size_t)idx)*EDGE_DIM + threadIdx.x];
    __syncthreads();
    float v;
    if (i == j) {
        v = nb[d];
        #pragma unroll
        for (int e = 0; e < IN_DIM; e++) v = fmaf(sx[e], nW[e*DD + d], v);
    } else {
        bool m;
        int mm = g_mask_mode;
        if (mm == 0)      m = ((const int*)mask)[idx] != 0;
        else if (mm == 1) m = ((const unsigned char*)mask)[idx] != 0;
        else              m = ((const float*)mask)[idx] != 0.f;
        if (m) {
            v = eb[d];
            #pragma unroll
            for (int e = 0; e < EDGE_DIM; e++) v = fmaf(se[e], eW[e*DD + d], v);
        } else {
            v = noe[d];
        }
    }
    g_tok[(size_t)idx*DD + d] = v;
}

// ================= mma.sync bf16 GEMM (split hi/lo, 3-term, ldmatrix) =================
#define BKC 64
#define APAD 72           // smem row stride in bf16 (+8 pad); 144B keeps ldmatrix conflict-free
#define TILE_ELEMS (128*APAD)
#define MMA_SMEM (4*TILE_ELEMS*2)   // 73728 bytes

__global__ __launch_bounds__(256, 2)
void mma_gemm_kernel(const float* __restrict__ A,
                     const __nv_bfloat16* __restrict__ BTh,
                     const __nv_bfloat16* __restrict__ BTl,
                     const float* __restrict__ bias, const float* __restrict__ res,
                     const float* __restrict__ lng, const float* __restrict__ lnb,
                     float* __restrict__ C, int Kt, int Nt, int relu) {
    extern __shared__ __align__(16) char smem[];
    __nv_bfloat16* Ah = (__nv_bfloat16*)smem;
    __nv_bfloat16* Al = Ah + TILE_ELEMS;
    __nv_bfloat16* Bh = Al + TILE_ELEMS;
    __nv_bfloat16* Bl = Bh + TILE_ELEMS;

    int t   = threadIdx.x;
    int wid = t >> 5, lid = t & 31;
    int g   = lid >> 2, tg = lid & 3;
    int wm0 = (wid >> 1) * 32;
    int wn0 = (wid & 1) * 64;
    int bn  = blockIdx.x << 7;
    int bm  = blockIdx.y << 7;

    // ldmatrix per-lane base addresses (byte, shared space)
    uint32_t smb = smem_u32(smem);
    // A: lanes 0-15 -> rows 0-15 at k+0; lanes 16-31 -> rows 0-15 at k+8
    uint32_t aAddrH = smb + (uint32_t)(((wm0 + (lid & 15))*APAD + (lid >> 4)*8) * 2);
    uint32_t aAddrL = aAddrH + TILE_ELEMS*2;
    // B: lanes/8 -> {nt k0, nt k8, nt+1 k0, nt+1 k8}
    uint32_t bAddrH = smb + (uint32_t)(2*TILE_ELEMS*2 +
                       ((wn0 + ((lid >> 4) & 1)*8 + (lid & 7))*APAD + ((lid >> 3) & 1)*8) * 2);
    uint32_t bAddrL = bAddrH + TILE_ELEMS*2;

    float acc[2][8][4];
    #pragma unroll
    for (int mt = 0; mt < 2; mt++)
        #pragma unroll
        for (int nt = 0; nt < 8; nt++)
            #pragma unroll
            for (int rr = 0; rr < 4; rr++) acc[mt][nt][rr] = 0.f;

    int lr = t >> 1;
    int cb = (t & 1) << 5;

    for (int k0 = 0; k0 < Kt; k0 += BKC) {
        const float* ap = A + (size_t)(bm + lr)*Kt + k0 + cb;
        __nv_bfloat16* ahp = Ah + lr*APAD + cb;
        __nv_bfloat16* alp = Al + lr*APAD + cb;
        #pragma unroll
        for (int u = 0; u < 8; u++) {
            float4 v = *(const float4*)(ap + u*4);
            __nv_bfloat16 h0,h1,h2,h3,l0,l1,l2,l3;
            bsplit(v.x,h0,l0); bsplit(v.y,h1,l1);
            bsplit(v.z,h2,l2); bsplit(v.w,h3,l3);
            *(uint2*)(ahp + u*4) = make_uint2(pack2bf(h0,h1), pack2bf(h2,h3));
            *(uint2*)(alp + u*4) = make_uint2(pack2bf(l0,l1), pack2bf(l2,l3));
        }
        const __nv_bfloat16* bhp = BTh + (size_t)(bn + lr)*Kt + k0 + cb;
        const __nv_bfloat16* blp = BTl + (size_t)(bn + lr)*Kt + k0 + cb;
        __nv_bfloat16* dbh = Bh + lr*APAD + cb;
        __nv_bfloat16* dbl = Bl + lr*APAD + cb;
        #pragma unroll
        for (int u = 0; u < 4; u++) {
            *(uint4*)(dbh + u*8) = *(const uint4*)(bhp + u*8);
            *(uint4*)(dbl + u*8) = *(const uint4*)(blp + u*8);
        }
        __syncthreads();
        #pragma unroll
        for (int ks = 0; ks < 4; ks++) {
            uint32_t ah[2][4], al[2][4];
            #pragma unroll
            for (int mt = 0; mt < 2; mt++) {
                uint32_t koff = (uint32_t)((mt*16*APAD + ks*16) * 2);
                ldsm4(aAddrH + koff, ah[mt]);
                ldsm4(aAddrL + koff, al[mt]);
            }
            #pragma unroll
            for (int np = 0; np < 4; np++) {
                uint32_t koff = (uint32_t)((np*16*APAD + ks*16) * 2);
                uint32_t bh4[4], bl4[4];
                ldsm4(bAddrH + koff, bh4);
                ldsm4(bAddrL + koff, bl4);
                #pragma unroll
                for (int half = 0; half < 2; half++) {
                    int nt = np*2 + half;
                    #pragma unroll
                    for (int mt = 0; mt < 2; mt++) {
                        mma16816(acc[mt][nt], ah[mt], bh4 + half*2);
                        mma16816(acc[mt][nt], ah[mt], bl4 + half*2);
                        mma16816(acc[mt][nt], al[mt], bh4 + half*2);
                    }
                }
            }
        }
        __syncthreads();
    }

    // ---------------- epilogue: bias / residual / relu ----------------
    #pragma unroll
    for (int nt = 0; nt < 8; nt++) {
        int colg = bn + wn0 + nt*8 + tg*2;
        float b0 = 0.f, b1 = 0.f;
        if (bias) { b0 = bias[colg]; b1 = bias[colg+1]; }
        #pragma unroll
        for (int mt = 0; mt < 2; mt++) {
            #pragma unroll
            for (int rp = 0; rp < 2; rp++) {
                int rowg = bm + wm0 + mt*16 + rp*8 + g;
                float v0 = acc[mt][nt][rp*2]   + b0;
                float v1 = acc[mt][nt][rp*2+1] + b1;
                if (res) {
                    float2 rv = *(const float2*)(res + (size_t)rowg*Nt + colg);
                    v0 += rv.x; v1 += rv.y;
                }
                if (relu) { v0 = fmaxf(v0, 0.f); v1 = fmaxf(v1, 0.f); }
                acc[mt][nt][rp*2]   = v0;
                acc[mt][nt][rp*2+1] = v1;
            }
        }
    }

    if (lng) {
        float* rs = (float*)smem;        // [128][2]
        float* rq = rs + 256;            // [128][2]
        #pragma unroll
        for (int mt = 0; mt < 2; mt++) {
            #pragma unroll
            for (int rp = 0; rp < 2; rp++) {
                float s = 0.f, q = 0.f;
                #pragma unroll
                for (int nt = 0; nt < 8; nt++) {
                    float v0 = acc[mt][nt][rp*2], v1 = acc[mt][nt][rp*2+1];
                    s += v0 + v1;
                    q += v0*v0 + v1*v1;
                }
                s += __shfl_xor_sync(0xffffffffu, s, 1);
                s += __shfl_xor_sync(0xffffffffu, s, 2);
                q += __shfl_xor_sync(0xffffffffu, q, 1);
                q += __shfl_xor_sync(0xffffffffu, q, 2);
                if (tg == 0) {
                    int row = wm0 + mt*16 + rp*8 + g;
                    rs[row*2 + (wid & 1)] = s;
                    rq[row*2 + (wid & 1)] = q;
                }
            }
        }
        __syncthreads();
        #pragma unroll
        for (int mt = 0; mt < 2; mt++) {
            #pragma unroll
            for (int rp = 0; rp < 2; rp++) {
                int row = wm0 + mt*16 + rp*8 + g;
                float s = rs[row*2] + rs[row*2+1];
                float q = rq[row*2] + rq[row*2+1];
                float mean = s * 0.0078125f;
                float rstd = rsqrtf(q * 0.0078125f - mean*mean + 1e-5f);
                size_t rowoff = (size_t)(bm + row)*Nt;
                #pragma unroll
                for (int nt = 0; nt < 8; nt++) {
                    int col = wn0 + nt*8 + tg*2;
                    float2 gg = *(const float2*)(lng + col);
                    float2 gb = *(const float2*)(lnb + col);
                    float v0 = (acc[mt][nt][rp*2]   - mean)*rstd*gg.x + gb.x;
                    float v1 = (acc[mt][nt][rp*2+1] - mean)*rstd*gg.y + gb.y;
                    *(float2*)(C + rowoff + bn + col) = make_float2(v0, v1);
                }
            }
        }
    } else {
        #pragma unroll
        for (int mt = 0; mt < 2; mt++) {
            #pragma unroll
            for (int rp = 0; rp < 2; rp++) {
                int rowg = bm + wm0 + mt*16 + rp*8 + g;
                size_t rowoff = (size_t)rowg*Nt;
                #pragma unroll
                for (int nt = 0; nt < 8; nt++) {
                    int colg = bn + wn0 + nt*8 + tg*2;
                    *(float2*)(C + rowoff + colg) =
                        make_float2(acc[mt][nt][rp*2], acc[mt][nt][rp*2+1]);
                }
            }
        }
    }
}

// ---------------- scores: s[b,h,i,l,j] = (1/SCALE) * q[b,i,l,h,:] . k[b,l,j,h,:] ------
__global__ __launch_bounds__(256)
void score_kernel() {
    int bid = blockIdx.x;                  // bh*64 + l
    int l  = bid & 63;
    int bh = bid >> 6;
    int h  = bh & 3;
    int b  = bh >> 2;
    __shared__ float Qs[64][33];
    __shared__ float Ks[64][33];
    int t = threadIdx.x;
    for (int idx = t; idx < 64*32; idx += 256) {
        int r = idx >> 5, c = idx & 31;
        Qs[r][c] = g_qkv[((size_t)((b*NN + r)*NN + l))*512 +       h*DHH + c]; // q, r=i
        Ks[r][c] = g_qkv[((size_t)((b*NN + l)*NN + r))*512 + 128 + h*DHH + c]; // k, r=j
    }
    __syncthreads();
    int tj = t & 15, ti = t >> 4;
    float acc[4][4] = {};
    #pragma unroll
    for (int c = 0; c < 32; c++) {
        float q[4], k[4];
        #pragma unroll
        for (int u = 0; u < 4; u++) { q[u] = Qs[ti*4+u][c]; k[u] = Ks[tj*4+u][c]; }
        #pragma unroll
        for (int i2 = 0; i2 < 4; i2++)
            #pragma unroll
            for (int j2 = 0; j2 < 4; j2++)
                acc[i2][j2] = fmaf(q[i2], k[j2], acc[i2][j2]);
    }
    #pragma unroll
    for (int i2 = 0; i2 < 4; i2++) {
        int i = ti*4 + i2;
        float4 v = make_float4(acc[i2][0]*INV_SCALE, acc[i2][1]*INV_SCALE,
                               acc[i2][2]*INV_SCALE, acc[i2][3]*INV_SCALE);
        *(float4*)(g_s + ((size_t)(bh*NN + i)*NN + l)*NN + tj*4) = v;
    }
}

// ---------------- softmax over l on s[b][h][i][l][j] (contiguous tile) ------------
__global__ __launch_bounds__(256)
void softmax_kernel() {
    int bid = blockIdx.x;            // bh*64 + i
    size_t base = (size_t)bid * 4096;
    int t = threadIdx.x;
    int j = t & 63, lq = t >> 6;     // 4 l-groups of 16
    __shared__ float pm[4][64], ps[4][64];
    float v[16];
    float mx = -1e30f;
    #pragma unroll
    for (int u = 0; u < 16; u++) {
        v[u] = g_s[base + (size_t)(lq*16 + u)*64 + j];
        mx = fmaxf(mx, v[u]);
    }
    pm[lq][j] = mx;
    __syncthreads();
    mx = fmaxf(fmaxf(pm[0][j], pm[1][j]), fmaxf(pm[2][j], pm[3][j]));
    float s = 0.f;
    #pragma unroll
    for (int u = 0; u < 16; u++) { v[u] = __expf(v[u] - mx); s += v[u]; }
    ps[lq][j] = s;
    __syncthreads();
    float inv = 1.f / (ps[0][j] + ps[1][j] + ps[2][j] + ps[3][j]);
    #pragma unroll
    for (int u = 0; u < 16; u++)
        g_s[base + (size_t)(lq*16 + u)*64 + j] = v[u] * inv;
}

// ---------------- tiled attn_o ----------------
#define AT_V1 0                         // [i][l][36] floats
#define AT_V2 (16*16*36)                // [l][j][36]
#define AT_A  (2*16*16*36)              // [l][i][16]
#define ATTN_SMEM ((2*16*16*36 + 16*16*16)*4)

__global__ __launch_bounds__(256)
void attn_o_kernel() {
    extern __shared__ __align__(16) float sm[];
    float* v1s = sm + AT_V1;
    float* v2s = sm + AT_V2;
    float* as_ = sm + AT_A;
    int bx = blockIdx.x;
    int jt = bx & 3;
    int it = (bx >> 2) & 3;
    int h  = (bx >> 4) & 3;
    int b  = bx >> 6;
    int bh = b*HH + h;
    int i0 = it*16, j0 = jt*16;
    int t = threadIdx.x;
    int ti = t >> 4, tj = t & 15;

    float acc[32];
    #pragma unroll
    for (int d = 0; d < 32; d++) acc[d] = 0.f;

    for (int lc = 0; lc < 4; lc++) {
        int l0 = lc*16;
        #pragma unroll
        for (int k = 0; k < 8; k++) {
            int fid = t + k*256;
            int dq = fid & 7, l = (fid >> 3) & 15, i_ = fid >> 7;
            float4 v = *(const float4*)(g_qkv +
                ((size_t)((b*NN + i0 + i_)*NN + l0 + l))*512 + 256 + h*DHH + dq*4);
            *(float4*)(v1s + (i_*16 + l)*36 + dq*4) = v;
        }
        #pragma unroll
        for (int k = 0; k < 8; k++) {
            int fid = t + k*256;
            int dq = fid & 7, j_ = (fid >> 3) & 15, l_ = fid >> 7;
            float4 v = *(const float4*)(g_qkv +
                ((size_t)((b*NN + l0 + l_)*NN + j0 + j_))*512 + 384 + h*DHH + dq*4);
            *(float4*)(v2s + (l_*16 + j_)*36 + dq*4) = v;
        }
        #pragma unroll
        for (int k = 0; k < 4; k++) {
            int fid = t + k*256;
            int jq = fid & 3, i_ = (fid >> 2) & 15, l_ = fid >> 6;
            float4 v = *(const float4*)(g_s +
                ((size_t)(bh*NN + i0 + i_)*NN + l0 + l_)*NN + j0 + jq*4);
            *(float4*)(as_ + (l_*16 + i_)*16 + jq*4) = v;
        }
        __syncthreads();
        #pragma unroll 4
        for (int l = 0; l < 16; l++) {
            float a = as_[(l*16 + ti)*16 + tj];
            const float* p1 = v1s + (ti*16 + l)*36;
            const float* p2 = v2s + (l*16 + tj)*36;
            #pragma unroll
            for (int dq = 0; dq < 8; dq++) {
                float4 x = *(const float4*)(p1 + dq*4);
                float4 y = *(const float4*)(p2 + dq*4);
                acc[dq*4+0] = fmaf(a, x.x * y.x, acc[dq*4+0]);
                acc[dq*4+1] = fmaf(a, x.y * y.y, acc[dq*4+1]);
                acc[dq*4+2] = fmaf(a, x.z * y.z, acc[dq*4+2]);
                acc[dq*4+3] = fmaf(a, x.w * y.w, acc[dq*4+3]);
            }
        }
        __syncthreads();
    }
    float* op = g_o + ((size_t)((b*NN + i0 + ti)*NN + j0 + tj) << 7) + h*DHH;
    #pragma unroll
    for (int dq = 0; dq < 8; dq++)
        *(float4*)(op + dq*4) = make_float4(acc[dq*4], acc[dq*4+1], acc[dq*4+2], acc[dq*4+3]);
}

// ---------------- final: out[b,n] = diag_tok . Wout + bout ----------------
__global__ __launch_bounds__(128)
void out_kernel(const float* __restrict__ Wout, const float* __restrict__ bout,
                float* __restrict__ out) {
    int bn = blockIdx.x;             // b*64 + n
    int n = bn & 63;
    int d = threadIdx.x;
    float v = g_tok[((size_t)bn*NN + n)*DD + d] * Wout[d];
    __shared__ float r[4];
    #pragma unroll
    for (int o = 16; o > 0; o >>= 1) v += __shfl_xor_sync(0xffffffffu, v, o);
    if ((d & 31) == 0) r[d >> 5] = v;
    __syncthreads();
    if (d == 0) out[bn] = r[0] + r[1] + r[2] + r[3] + bout[0];
}

// ---------------- host driver ----------------
extern "C" void kernel_launch(void* const* d_in, const int* in_sizes, int n_in,
                              void* d_out, int out_size) {
    const float* x    = (const float*)d_in[0];
    const float* ea   = (const float*)d_in[1];
    const void*  mask = d_in[2];
    const float* nW   = (const float*)d_in[3];
    const float* nb   = (const float*)d_in[4];
    const float* eW   = (const float*)d_in[5];
    const float* eb   = (const float*)d_in[6];
    const float* noe  = (const float*)d_in[7];
    const float* Wq   = (const float*)d_in[8];
    const float* Wk   = (const float*)d_in[9];
    const float* Wv1  = (const float*)d_in[10];
    const float* Wv2  = (const float*)d_in[11];
    const float* Wo   = (const float*)d_in[12];
    const float* bo   = (const float*)d_in[13];
    const float* ln1g = (const float*)d_in[14];
    const float* ln1b = (const float*)d_in[15];
    const float* W1   = (const float*)d_in[16];
    const float* b1   = (const float*)d_in[17];
    const float* W2   = (const float*)d_in[18];
    const float* b2   = (const float*)d_in[19];
    const float* ln2g = (const float*)d_in[20];
    const float* ln2b = (const float*)d_in[21];
    const float* Wout = (const float*)d_in[22];
    const float* bout = (const float*)d_in[23];

    float *tok, *qkv, *o, *hid;
    __nv_bfloat16 *wqkvh, *wqkvl, *woh, *wol, *w1h, *w1l, *w2h, *w2l;
    cudaGetSymbolAddress((void**)&tok,   g_tok);
    cudaGetSymbolAddress((void**)&qkv,   g_qkv);
    cudaGetSymbolAddress((void**)&o,     g_o);
    cudaGetSymbolAddress((void**)&hid,   g_hid);
    cudaGetSymbolAddress((void**)&wqkvh, g_wqkvT_h);
    cudaGetSymbolAddress((void**)&wqkvl, g_wqkvT_l);
    cudaGetSymbolAddress((void**)&woh,   g_woT_h);
    cudaGetSymbolAddress((void**)&wol,   g_woT_l);
    cudaGetSymbolAddress((void**)&w1h,   g_w1T_h);
    cudaGetSymbolAddress((void**)&w1l,   g_w1T_l);
    cudaGetSymbolAddress((void**)&w2h,   g_w2T_h);
    cudaGetSymbolAddress((void**)&w2l,   g_w2T_l);

    cudaFuncSetAttribute(mma_gemm_kernel,
                         cudaFuncAttributeMaxDynamicSharedMemorySize, MMA_SMEM);
    cudaFuncSetAttribute(attn_o_kernel,
                         cudaFuncAttributeMaxDynamicSharedMemorySize, ATTN_SMEM);

    detect_mask_kernel<<<1, 256>>>((const unsigned char*)mask);
    pack_all_kernel<<<2496, 256>>>(Wq, Wk, Wv1, Wv2, Wo, W1, W2,
                                   wqkvh, wqkvl, woh, wol, w1h, w1l, w2h, w2l);
    embed_kernel<<<MROWS, DD>>>(x, ea, mask, nW, nb, eW, eb, noe);

    dim3 gN128(1, MROWS/128);
    dim3 gN512(4, MROWS/128);

    for (int l = 0; l < LL; l++) {
        const __nv_bfloat16* wqh = wqkvh + (size_t)l*512*128;
        const __nv_bfloat16* wql = wqkvl + (size_t)l*512*128;
        const __nv_bfloat16* wo_h = woh + (size_t)l*128*128;
        const __nv_bfloat16* wo_l = wol + (size_t)l*128*128;
        const __nv_bfloat16* w1_h = w1h + (size_t)l*512*128;
        const __nv_bfloat16* w1_l = w1l + (size_t)l*512*128;
        const __nv_bfloat16* w2_h = w2h + (size_t)l*128*512;
        const __nv_bfloat16* w2_l = w2l + (size_t)l*128*512;
        const float* bo_l  = bo  + (size_t)l*DD;
        const float* g1_l  = ln1g + (size_t)l*DD;
        const float* b1l_l = ln1b + (size_t)l*DD;
        const float* bf1_l = b1  + (size_t)l*FF;
        const float* bf2_l = b2  + (size_t)l*DD;
        const float* g2_l  = ln2g + (size_t)l*DD;
        const float* b2l_l = ln2b + (size_t)l*DD;

        // fused QKV projection
        mma_gemm_kernel<<<gN512, 256, MMA_SMEM>>>(tok, wqh, wql,
            nullptr, nullptr, nullptr, nullptr, qkv, 128, 512, 0);

        score_kernel<<<BB*HH*NN, 256>>>();
        softmax_kernel<<<BB*HH*NN, 256>>>();
        attn_o_kernel<<<512, 256, ATTN_SMEM>>>();

        // o-projection + bias + residual + LN1
        mma_gemm_kernel<<<gN128, 256, MMA_SMEM>>>(o, wo_h, wo_l,
            bo_l, tok, g1_l, b1l_l, tok, 128, 128, 0);
        // FFN up + relu
        mma_gemm_kernel<<<gN512, 256, MMA_SMEM>>>(tok, w1_h, w1_l,
            bf1_l, nullptr, nullptr, nullptr, hid, 128, 512, 1);
        // FFN down + bias + residual + LN2
        mma_gemm_kernel<<<gN128, 256, MMA_SMEM>>>(hid, w2_h, w2_l,
            bf2_l, tok, g2_l, b2l_l, tok, 512, 128, 0);
    }

    out_kernel<<<BB*NN, 128>>>(Wout, bout, (float*)d_out);
}

// round 8
// speedup vs baseline: 2.1000x; 1.1025x over previous
#include <cuda_runtime.h>
#include <cuda_bf16.h>
#include <math.h>
#include <stdint.h>

// ---------------- problem constants ----------------
#define BB 8
#define NN 64
#define IN_DIM 16
#define EDGE_DIM 8
#define DD 128
#define HH 4
#define DHH 32
#define LL 3
#define FF 512
#define MROWS (BB*NN*NN)          // 32768
static const float INV_SCALE = 0.17677669529663687f; // 1/sqrt(32)

// ---------------- scratch (device globals; no runtime alloc) ----------------
__device__ float g_tok  [(size_t)MROWS*DD];
__device__ float g_qkv  [(size_t)MROWS*512];          // q|k|v1|v2 packed along N
__device__ float g_s    [(size_t)BB*HH*NN*NN*NN];     // [b][h][i][l][j]
// bf16 hi/lo activation copies (GEMM A operands)
__device__ __nv_bfloat16 g_tok_h[(size_t)MROWS*DD];
__device__ __nv_bfloat16 g_tok_l[(size_t)MROWS*DD];
__device__ __nv_bfloat16 g_o_h  [(size_t)MROWS*DD];
__device__ __nv_bfloat16 g_o_l  [(size_t)MROWS*DD];
__device__ __nv_bfloat16 g_hid_h[(size_t)MROWS*FF];
__device__ __nv_bfloat16 g_hid_l[(size_t)MROWS*FF];
// transposed + bf16-split weights: layout [l][N][K]
__device__ __nv_bfloat16 g_wqkvT_h[(size_t)LL*512*128];
__device__ __nv_bfloat16 g_wqkvT_l[(size_t)LL*512*128];
__device__ __nv_bfloat16 g_woT_h  [(size_t)LL*128*128];
__device__ __nv_bfloat16 g_woT_l  [(size_t)LL*128*128];
__device__ __nv_bfloat16 g_w1T_h  [(size_t)LL*512*128];
__device__ __nv_bfloat16 g_w1T_l  [(size_t)LL*512*128];
__device__ __nv_bfloat16 g_w2T_h  [(size_t)LL*128*512];
__device__ __nv_bfloat16 g_w2T_l  [(size_t)LL*128*512];
__device__ int g_mask_mode;                            // 0=int32, 1=uint8, 2=float32

// ---------------- helpers ----------------
__device__ __forceinline__ void bsplit(float v, __nv_bfloat16& h, __nv_bfloat16& l) {
    h = __float2bfloat16(v);
    l = __float2bfloat16(v - __bfloat162float(h));
}
__device__ __forceinline__ uint32_t pack2bf(__nv_bfloat16 a, __nv_bfloat16 b) {
    return (uint32_t)__bfloat16_as_ushort(a) | ((uint32_t)__bfloat16_as_ushort(b) << 16);
}
__device__ __forceinline__ uint32_t smem_u32(const void* p) {
    uint32_t a;
    asm("{ .reg .u64 t; cvta.to.shared.u64 t, %1; cvt.u32.u64 %0, t; }" : "=r"(a) : "l"(p));
    return a;
}
// D += A*B  (m16n8k16, bf16 in, f32 acc)
__device__ __forceinline__ void mma16816(float* c, const uint32_t* a, const uint32_t* b) {
    asm volatile(
        "mma.sync.aligned.m16n8k16.row.col.f32.bf16.bf16.f32 "
        "{%0,%1,%2,%3}, {%4,%5,%6,%7}, {%8,%9}, {%0,%1,%2,%3};"
        : "+f"(c[0]), "+f"(c[1]), "+f"(c[2]), "+f"(c[3])
        : "r"(a[0]), "r"(a[1]), "r"(a[2]), "r"(a[3]), "r"(b[0]), "r"(b[1]));
}
__device__ __forceinline__ void ldsm4(uint32_t addr, uint32_t* r) {
    asm volatile("ldmatrix.sync.aligned.m8n8.x4.shared.b16 {%0,%1,%2,%3}, [%4];"
        : "=r"(r[0]), "=r"(r[1]), "=r"(r[2]), "=r"(r[3]) : "r"(addr));
}
__device__ __forceinline__ void cpa16(uint32_t saddr, const void* g) {
    asm volatile("cp.async.cg.shared.global [%0], [%1], 16;" :: "r"(saddr), "l"(g));
}

// ---------------- mask dtype detector ----------------
__global__ void detect_mask_kernel(const unsigned char* __restrict__ m) {
    __shared__ int has3f, hasodd;
    if (threadIdx.x == 0) { has3f = 0; hasodd = 0; }
    __syncthreads();
    for (int i = threadIdx.x; i < 4096; i += blockDim.x) {
        unsigned char v = m[i];
        if (v == 0x3F) atomicOr(&has3f, 1);
        if (v != 0 && (i & 3)) atomicOr(&hasodd, 1);
    }
    __syncthreads();
    if (threadIdx.x == 0) g_mask_mode = has3f ? 2 : (hasodd ? 1 : 0);
}

// ---------------- merged weight transpose + bf16 split ----------------
__global__ void pack_all_kernel(const float* __restrict__ Wq, const float* __restrict__ Wk,
                                const float* __restrict__ Wv1, const float* __restrict__ Wv2,
                                const float* __restrict__ Wo, const float* __restrict__ W1,
                                const float* __restrict__ W2,
                                __nv_bfloat16* __restrict__ qh, __nv_bfloat16* __restrict__ ql,
                                __nv_bfloat16* __restrict__ oh, __nv_bfloat16* __restrict__ ol,
                                __nv_bfloat16* __restrict__ h1, __nv_bfloat16* __restrict__ l1,
                                __nv_bfloat16* __restrict__ h2, __nv_bfloat16* __restrict__ l2) {
    int blk = blockIdx.x;
    const float* src; __nv_bfloat16 *dh, *dl;
    int K, N, dstN, nOff, idx;
    if (blk < 768) {
        int seg = blk / 192;
        idx = (blk - seg*192)*256 + threadIdx.x;
        src = (seg==0)?Wq:(seg==1)?Wk:(seg==2)?Wv1:Wv2;
        dh = qh; dl = ql; K = 128; N = 128; dstN = 512; nOff = seg*128;
    } else if (blk < 960) {
        idx = (blk-768)*256 + threadIdx.x;
        src = Wo; dh = oh; dl = ol; K = 128; N = 128; dstN = 128; nOff = 0;
    } else if (blk < 1728) {
        idx = (blk-960)*256 + threadIdx.x;
        src = W1; dh = h1; dl = l1; K = 128; N = 512; dstN = 512; nOff = 0;
    } else {
        idx = (blk-1728)*256 + threadIdx.x;
        src = W2; dh = h2; dl = l2; K = 512; N = 128; dstN = 128; nOff = 0;
    }
    if (idx >= LL*N*K) return;
    int k = idx % K;
    int n = (idx / K) % N;
    int ll = idx / (K*N);
    float v = src[((size_t)ll*K + k)*N + n];
    __nv_bfloat16 vh, vl; bsplit(v, vh, vl);
    size_t o = ((size_t)ll*dstN + nOff + n)*K + k;
    dh[o] = vh; dl[o] = vl;
}

// ---------------- embedding (fp32 + hi/lo) ----------------
__global__ void embed_kernel(const float* __restrict__ x,
                             const float* __restrict__ ea,
                             const void*  __restrict__ mask,
                             const float* __restrict__ nW, const float* __restrict__ nb,
                             const float* __restrict__ eW, const float* __restrict__ eb,
                             const float* __restrict__ noe) {
    int idx = blockIdx.x;                 // b*N*N + i*N + j
    int j = idx & 63;
    int i = (idx >> 6) & 63;
    int b = idx >> 12;
    int d = threadIdx.x;                  // 0..127
    __shared__ float sx[IN_DIM];
    __shared__ float se[EDGE_DIM];
    if (threadIdx.x < IN_DIM)  sx[threadIdx.x] = x[(b*NN + i)*IN_DIM + threadIdx.x];
    if (threadIdx.x < EDGE_DIM) se[threadIdx.x] = ea[((size_t)idx)*EDGE_DIM + threadIdx.x];
    __syncthreads();
    float v;
    if (i == j) {
        v = nb[d];
        #pragma unroll
        for (int e = 0; e < IN_DIM; e++) v = fmaf(sx[e], nW[e*DD + d], v);
    } else {
        bool m;
        int mm = g_mask_mode;
        if (mm == 0)      m = ((const int*)mask)[idx] != 0;
        else if (mm == 1) m = ((const unsigned char*)mask)[idx] != 0;
        else              m = ((const float*)mask)[idx] != 0.f;
        if (m) {
            v = eb[d];
            #pragma unroll
            for (int e = 0; e < EDGE_DIM; e++) v = fmaf(se[e], eW[e*DD + d], v);
        } else {
            v = noe[d];
        }
    }
    size_t off = (size_t)idx*DD + d;
    g_tok[off] = v;
    __nv_bfloat16 vh, vl; bsplit(v, vh, vl);
    g_tok_h[off] = vh; g_tok_l[off] = vl;
}

// ================= cp.async double-buffered mma.sync bf16 GEMM =================
// C = A @ W ; A given pre-split (Agh/Agl [M][Kt] bf16), W pre-split transposed
// (Bgh/Bgl [Nt][Kt]). CTA tile 128x128, K chunk 64, 2-stage pipeline.
// smem tile: 128 rows x 128B, XOR swizzle: byte = row*128 + ((c16 ^ (row&7))<<4)
#define TILE_B 16384
#define STAGE_B (4*TILE_B)
#define GSMEM (2*STAGE_B)        // 131072 bytes

__global__ __launch_bounds__(256)
void mma_gemm_kernel(const __nv_bfloat16* __restrict__ Agh,
                     const __nv_bfloat16* __restrict__ Agl,
                     const __nv_bfloat16* __restrict__ Bgh,
                     const __nv_bfloat16* __restrict__ Bgl,
                     const float* __restrict__ bias, const float* __restrict__ res,
                     const float* __restrict__ lng, const float* __restrict__ lnb,
                     float* __restrict__ Cf,
                     __nv_bfloat16* __restrict__ Ch, __nv_bfloat16* __restrict__ Cl,
                     int Kt, int Nt, int relu) {
    extern __shared__ __align__(16) char smem[];
    uint32_t smb = smem_u32(smem);
    int t   = threadIdx.x;
    int wid = t >> 5, lid = t & 31;
    int g   = lid >> 2, tg = lid & 3;
    int wm0 = (wid >> 1) * 32;
    int wn0 = (wid & 1) * 64;
    int bn  = blockIdx.x << 7;
    int bm  = blockIdx.y << 7;

    // cp.async segment mapping (4 segs per thread per tile)
    int srow = t >> 1;                    // not used directly; per-seg below
    (void)srow;

    float acc[2][8][4];
    #pragma unroll
    for (int mt = 0; mt < 2; mt++)
        #pragma unroll
        for (int nt = 0; nt < 8; nt++)
            #pragma unroll
            for (int rr = 0; rr < 4; rr++) acc[mt][nt][rr] = 0.f;

    int nch = Kt >> 6;

    // ---- chunk loader ----
    auto load_chunk = [&](int ch, int stg) {
        int k0 = ch << 6;
        uint32_t sb = smb + stg*STAGE_B;
        const __nv_bfloat16* srcs[4] = { Agh, Agl, Bgh, Bgl };
        #pragma unroll
        for (int tile = 0; tile < 4; tile++) {
            const __nv_bfloat16* src = srcs[tile];
            int rbase = (tile < 2) ? bm : bn;
            uint32_t tb = sb + tile*TILE_B;
            #pragma unroll
            for (int p = 0; p < 4; p++) {
                int seg = t + p*256;
                int row = seg >> 3, c16 = seg & 7;
                const __nv_bfloat16* gp = src + (size_t)(rbase + row)*Kt + k0 + c16*8;
                uint32_t sa = tb + row*128 + (((uint32_t)(c16 ^ (row & 7))) << 4);
                cpa16(sa, gp);
            }
        }
        asm volatile("cp.async.commit_group;" ::: "memory");
    };

    load_chunk(0, 0);
    for (int ch = 0; ch < nch; ch++) {
        if (ch + 1 < nch) {
            load_chunk(ch + 1, (ch + 1) & 1);
            asm volatile("cp.async.wait_group 1;" ::: "memory");
        } else {
            asm volatile("cp.async.wait_group 0;" ::: "memory");
        }
        __syncthreads();
        uint32_t sb = smb + (ch & 1)*STAGE_B;
        #pragma unroll
        for (int ks = 0; ks < 4; ks++) {
            uint32_t ah[2][4], al[2][4];
            int ac16 = ks*2 + (lid >> 4);
            #pragma unroll
            for (int mt = 0; mt < 2; mt++) {
                int row = wm0 + mt*16 + (lid & 15);
                uint32_t off = (uint32_t)(row*128) + (((uint32_t)(ac16 ^ (row & 7))) << 4);
                ldsm4(sb + off, ah[mt]);
                ldsm4(sb + TILE_B + off, al[mt]);
            }
            int bc16 = ks*2 + ((lid >> 3) & 1);
            #pragma unroll
            for (int np = 0; np < 4; np++) {
                int row = wn0 + np*16 + ((lid >> 4) & 1)*8 + (lid & 7);
                uint32_t off = (uint32_t)(row*128) + (((uint32_t)(bc16 ^ (row & 7))) << 4);
                uint32_t bh4[4], bl4[4];
                ldsm4(sb + 2*TILE_B + off, bh4);
                ldsm4(sb + 3*TILE_B + off, bl4);
                #pragma unroll
                for (int half = 0; half < 2; half++) {
                    int nt = np*2 + half;
                    #pragma unroll
                    for (int mt = 0; mt < 2; mt++) {
                        mma16816(acc[mt][nt], ah[mt], bh4 + half*2);
                        mma16816(acc[mt][nt], ah[mt], bl4 + half*2);
                        mma16816(acc[mt][nt], al[mt], bh4 + half*2);
                    }
                }
            }
        }
        __syncthreads();
    }

    // ---------------- epilogue: bias / residual / relu ----------------
    #pragma unroll
    for (int nt = 0; nt < 8; nt++) {
        int colg = bn + wn0 + nt*8 + tg*2;
        float b0 = 0.f, b1 = 0.f;
        if (bias) { b0 = bias[colg]; b1 = bias[colg+1]; }
        #pragma unroll
        for (int mt = 0; mt < 2; mt++) {
            #pragma unroll
            for (int rp = 0; rp < 2; rp++) {
                int rowg = bm + wm0 + mt*16 + rp*8 + g;
                float v0 = acc[mt][nt][rp*2]   + b0;
                float v1 = acc[mt][nt][rp*2+1] + b1;
                if (res) {
                    float2 rv = *(const float2*)(res + (size_t)rowg*Nt + colg);
                    v0 += rv.x; v1 += rv.y;
                }
                if (relu) { v0 = fmaxf(v0, 0.f); v1 = fmaxf(v1, 0.f); }
                acc[mt][nt][rp*2]   = v0;
                acc[mt][nt][rp*2+1] = v1;
            }
        }
    }

    if (lng) {
        // LN over last dim; only used with Nt==128.
        float* rs = (float*)smem;        // [128][2]
        float* rq = rs + 256;            // [128][2]
        #pragma unroll
        for (int mt = 0; mt < 2; mt++) {
            #pragma unroll
            for (int rp = 0; rp < 2; rp++) {
                float s = 0.f, q = 0.f;
                #pragma unroll
                for (int nt = 0; nt < 8; nt++) {
                    float v0 = acc[mt][nt][rp*2], v1 = acc[mt][nt][rp*2+1];
                    s += v0 + v1;
                    q += v0*v0 + v1*v1;
                }
                s += __shfl_xor_sync(0xffffffffu, s, 1);
                s += __shfl_xor_sync(0xffffffffu, s, 2);
                q += __shfl_xor_sync(0xffffffffu, q, 1);
                q += __shfl_xor_sync(0xffffffffu, q, 2);
                if (tg == 0) {
                    int row = wm0 + mt*16 + rp*8 + g;
                    rs[row*2 + (wid & 1)] = s;
                    rq[row*2 + (wid & 1)] = q;
                }
            }
        }
        __syncthreads();
        #pragma unroll
        for (int mt = 0; mt < 2; mt++) {
            #pragma unroll
            for (int rp = 0; rp < 2; rp++) {
                int row = wm0 + mt*16 + rp*8 + g;
                float s = rs[row*2] + rs[row*2+1];
                float q = rq[row*2] + rq[row*2+1];
                float mean = s * 0.0078125f;
                float rstd = rsqrtf(q * 0.0078125f - mean*mean + 1e-5f);
                size_t rowoff = (size_t)(bm + row)*Nt;
                #pragma unroll
                for (int nt = 0; nt < 8; nt++) {
                    int col = wn0 + nt*8 + tg*2;
                    float2 gg = *(const float2*)(lng + col);
                    float2 gb = *(const float2*)(lnb + col);
                    float v0 = (acc[mt][nt][rp*2]   - mean)*rstd*gg.x + gb.x;
                    float v1 = (acc[mt][nt][rp*2+1] - mean)*rstd*gg.y + gb.y;
                    *(float2*)(Cf + rowoff + bn + col) = make_float2(v0, v1);
                    __nv_bfloat16 h0,l0,h1,l1;
                    bsplit(v0,h0,l0); bsplit(v1,h1,l1);
                    *(uint32_t*)(Ch + rowoff + bn + col) = pack2bf(h0,h1);
                    *(uint32_t*)(Cl + rowoff + bn + col) = pack2bf(l0,l1);
                }
            }
        }
    } else {
        #pragma unroll
        for (int mt = 0; mt < 2; mt++) {
            #pragma unroll
            for (int rp = 0; rp < 2; rp++) {
                int rowg = bm + wm0 + mt*16 + rp*8 + g;
                size_t rowoff = (size_t)rowg*Nt;
                #pragma unroll
                for (int nt = 0; nt < 8; nt++) {
                    int colg = bn + wn0 + nt*8 + tg*2;
                    float v0 = acc[mt][nt][rp*2], v1 = acc[mt][nt][rp*2+1];
                    if (Cf) *(float2*)(Cf + rowoff + colg) = make_float2(v0, v1);
                    if (Ch) {
                        __nv_bfloat16 h0,l0,h1,l1;
                        bsplit(v0,h0,l0); bsplit(v1,h1,l1);
                        *(uint32_t*)(Ch + rowoff + colg) = pack2bf(h0,h1);
                        *(uint32_t*)(Cl + rowoff + colg) = pack2bf(l0,l1);
                    }
                }
            }
        }
    }
}

// ---------------- scores: s[b,h,i,l,j] = (1/SCALE) * q[b,i,l,h,:] . k[b,l,j,h,:] ------
__global__ __launch_bounds__(256)
void score_kernel() {
    int bid = blockIdx.x;                  // bh*64 + l
    int l  = bid & 63;
    int bh = bid >> 6;
    int h  = bh & 3;
    int b  = bh >> 2;
    __shared__ float Qs[64][33];
    __shared__ float Ks[64][33];
    int t = threadIdx.x;
    for (int idx = t; idx < 64*32; idx += 256) {
        int r = idx >> 5, c = idx & 31;
        Qs[r][c] = g_qkv[((size_t)((b*NN + r)*NN + l))*512 +       h*DHH + c]; // q, r=i
        Ks[r][c] = g_qkv[((size_t)((b*NN + l)*NN + r))*512 + 128 + h*DHH + c]; // k, r=j
    }
    __syncthreads();
    int tj = t & 15, ti = t >> 4;
    float acc[4][4] = {};
    #pragma unroll
    for (int c = 0; c < 32; c++) {
        float q[4], k[4];
        #pragma unroll
        for (int u = 0; u < 4; u++) { q[u] = Qs[ti*4+u][c]; k[u] = Ks[tj*4+u][c]; }
        #pragma unroll
        for (int i2 = 0; i2 < 4; i2++)
            #pragma unroll
            for (int j2 = 0; j2 < 4; j2++)
                acc[i2][j2] = fmaf(q[i2], k[j2], acc[i2][j2]);
    }
    #pragma unroll
    for (int i2 = 0; i2 < 4; i2++) {
        int i = ti*4 + i2;
        float4 v = make_float4(acc[i2][0]*INV_SCALE, acc[i2][1]*INV_SCALE,
                               acc[i2][2]*INV_SCALE, acc[i2][3]*INV_SCALE);
        *(float4*)(g_s + ((size_t)(bh*NN + i)*NN + l)*NN + tj*4) = v;
    }
}

// ---------------- softmax over l on s[b][h][i][l][j] ----------------
__global__ __launch_bounds__(256)
void softmax_kernel() {
    int bid = blockIdx.x;            // bh*64 + i
    size_t base = (size_t)bid * 4096;
    int t = threadIdx.x;
    int j = t & 63, lq = t >> 6;
    __shared__ float pm[4][64], ps[4][64];
    float v[16];
    float mx = -1e30f;
    #pragma unroll
    for (int u = 0; u < 16; u++) {
        v[u] = g_s[base + (size_t)(lq*16 + u)*64 + j];
        mx = fmaxf(mx, v[u]);
    }
    pm[lq][j] = mx;
    __syncthreads();
    mx = fmaxf(fmaxf(pm[0][j], pm[1][j]), fmaxf(pm[2][j], pm[3][j]));
    float s = 0.f;
    #pragma unroll
    for (int u = 0; u < 16; u++) { v[u] = __expf(v[u] - mx); s += v[u]; }
    ps[lq][j] = s;
    __syncthreads();
    float inv = 1.f / (ps[0][j] + ps[1][j] + ps[2][j] + ps[3][j]);
    #pragma unroll
    for (int u = 0; u < 16; u++)
        g_s[base + (size_t)(lq*16 + u)*64 + j] = v[u] * inv;
}

// ---------------- tiled attn_o (writes split bf16 output) ----------------
#define AT_V1 0                         // [i][l][36] floats
#define AT_V2 (16*16*36)                // [l][j][36]
#define AT_A  (2*16*16*36)              // [l][i][16]
#define ATTN_SMEM ((2*16*16*36 + 16*16*16)*4)

__global__ __launch_bounds__(256)
void attn_o_kernel() {
    extern __shared__ __align__(16) float sm[];
    float* v1s = sm + AT_V1;
    float* v2s = sm + AT_V2;
    float* as_ = sm + AT_A;
    int bx = blockIdx.x;
    int jt = bx & 3;
    int it = (bx >> 2) & 3;
    int h  = (bx >> 4) & 3;
    int b  = bx >> 6;
    int bh = b*HH + h;
    int i0 = it*16, j0 = jt*16;
    int t = threadIdx.x;
    int ti = t >> 4, tj = t & 15;

    float acc[32];
    #pragma unroll
    for (int d = 0; d < 32; d++) acc[d] = 0.f;

    for (int lc = 0; lc < 4; lc++) {
        int l0 = lc*16;
        #pragma unroll
        for (int k = 0; k < 8; k++) {
            int fid = t + k*256;
            int dq = fid & 7, l = (fid >> 3) & 15, i_ = fid >> 7;
            float4 v = *(const float4*)(g_qkv +
                ((size_t)((b*NN + i0 + i_)*NN + l0 + l))*512 + 256 + h*DHH + dq*4);
            *(float4*)(v1s + (i_*16 + l)*36 + dq*4) = v;
        }
        #pragma unroll
        for (int k = 0; k < 8; k++) {
            int fid = t + k*256;
            int dq = fid & 7, j_ = (fid >> 3) & 15, l_ = fid >> 7;
            float4 v = *(const float4*)(g_qkv +
                ((size_t)((b*NN + l0 + l_)*NN + j0 + j_))*512 + 384 + h*DHH + dq*4);
            *(float4*)(v2s + (l_*16 + j_)*36 + dq*4) = v;
        }
        #pragma unroll
        for (int k = 0; k < 4; k++) {
            int fid = t + k*256;
            int jq = fid & 3, i_ = (fid >> 2) & 15, l_ = fid >> 6;
            float4 v = *(const float4*)(g_s +
                ((size_t)(bh*NN + i0 + i_)*NN + l0 + l_)*NN + j0 + jq*4);
            *(float4*)(as_ + (l_*16 + i_)*16 + jq*4) = v;
        }
        __syncthreads();
        #pragma unroll 4
        for (int l = 0; l < 16; l++) {
            float a = as_[(l*16 + ti)*16 + tj];
            const float* p1 = v1s + (ti*16 + l)*36;
            const float* p2 = v2s + (l*16 + tj)*36;
            #pragma unroll
            for (int dq = 0; dq < 8; dq++) {
                float4 x = *(const float4*)(p1 + dq*4);
                float4 y = *(const float4*)(p2 + dq*4);
                acc[dq*4+0] = fmaf(a, x.x * y.x, acc[dq*4+0]);
                acc[dq*4+1] = fmaf(a, x.y * y.y, acc[dq*4+1]);
                acc[dq*4+2] = fmaf(a, x.z * y.z, acc[dq*4+2]);
                acc[dq*4+3] = fmaf(a, x.w * y.w, acc[dq*4+3]);
            }
        }
        __syncthreads();
    }
    size_t obase = ((size_t)((b*NN + i0 + ti)*NN + j0 + tj) << 7) + h*DHH;
    #pragma unroll
    for (int dq = 0; dq < 8; dq++) {
        __nv_bfloat16 h0,l0_,h1,l1,h2,l2,h3,l3;
        bsplit(acc[dq*4+0],h0,l0_); bsplit(acc[dq*4+1],h1,l1);
        bsplit(acc[dq*4+2],h2,l2);  bsplit(acc[dq*4+3],h3,l3);
        *(uint2*)(g_o_h + obase + dq*4) = make_uint2(pack2bf(h0,h1), pack2bf(h2,h3));
        *(uint2*)(g_o_l + obase + dq*4) = make_uint2(pack2bf(l0_,l1), pack2bf(l2,l3));
    }
}

// ---------------- final: out[b,n] = diag_tok . Wout + bout ----------------
__global__ __launch_bounds__(128)
void out_kernel(const float* __restrict__ Wout, const float* __restrict__ bout,
                float* __restrict__ out) {
    int bn = blockIdx.x;             // b*64 + n
    int n = bn & 63;
    int d = threadIdx.x;
    float v = g_tok[((size_t)bn*NN + n)*DD + d] * Wout[d];
    __shared__ float r[4];
    #pragma unroll
    for (int o = 16; o > 0; o >>= 1) v += __shfl_xor_sync(0xffffffffu, v, o);
    if ((d & 31) == 0) r[d >> 5] = v;
    __syncthreads();
    if (d == 0) out[bn] = r[0] + r[1] + r[2] + r[3] + bout[0];
}

// ---------------- host driver ----------------
extern "C" void kernel_launch(void* const* d_in, const int* in_sizes, int n_in,
                              void* d_out, int out_size) {
    const float* x    = (const float*)d_in[0];
    const float* ea   = (const float*)d_in[1];
    const void*  mask = d_in[2];
    const float* nW   = (const float*)d_in[3];
    const float* nb   = (const float*)d_in[4];
    const float* eW   = (const float*)d_in[5];
    const float* eb   = (const float*)d_in[6];
    const float* noe  = (const float*)d_in[7];
    const float* Wq   = (const float*)d_in[8];
    const float* Wk   = (const float*)d_in[9];
    const float* Wv1  = (const float*)d_in[10];
    const float* Wv2  = (const float*)d_in[11];
    const float* Wo   = (const float*)d_in[12];
    const float* bo   = (const float*)d_in[13];
    const float* ln1g = (const float*)d_in[14];
    const float* ln1b = (const float*)d_in[15];
    const float* W1   = (const float*)d_in[16];
    const float* b1   = (const float*)d_in[17];
    const float* W2   = (const float*)d_in[18];
    const float* b2   = (const float*)d_in[19];
    const float* ln2g = (const float*)d_in[20];
    const float* ln2b = (const float*)d_in[21];
    const float* Wout = (const float*)d_in[22];
    const float* bout = (const float*)d_in[23];

    float *tok, *qkv;
    __nv_bfloat16 *tokh, *tokl, *oh_, *ol_, *hidh, *hidl;
    __nv_bfloat16 *wqkvh, *wqkvl, *woh, *wol, *w1h, *w1l, *w2h, *w2l;
    cudaGetSymbolAddress((void**)&tok,   g_tok);
    cudaGetSymbolAddress((void**)&qkv,   g_qkv);
    cudaGetSymbolAddress((void**)&tokh,  g_tok_h);
    cudaGetSymbolAddress((void**)&tokl,  g_tok_l);
    cudaGetSymbolAddress((void**)&oh_,   g_o_h);
    cudaGetSymbolAddress((void**)&ol_,   g_o_l);
    cudaGetSymbolAddress((void**)&hidh,  g_hid_h);
    cudaGetSymbolAddress((void**)&hidl,  g_hid_l);
    cudaGetSymbolAddress((void**)&wqkvh, g_wqkvT_h);
    cudaGetSymbolAddress((void**)&wqkvl, g_wqkvT_l);
    cudaGetSymbolAddress((void**)&woh,   g_woT_h);
    cudaGetSymbolAddress((void**)&wol,   g_woT_l);
    cudaGetSymbolAddress((void**)&w1h,   g_w1T_h);
    cudaGetSymbolAddress((void**)&w1l,   g_w1T_l);
    cudaGetSymbolAddress((void**)&w2h,   g_w2T_h);
    cudaGetSymbolAddress((void**)&w2l,   g_w2T_l);

    cudaFuncSetAttribute(mma_gemm_kernel,
                         cudaFuncAttributeMaxDynamicSharedMemorySize, GSMEM);
    cudaFuncSetAttribute(attn_o_kernel,
                         cudaFuncAttributeMaxDynamicSharedMemorySize, ATTN_SMEM);

    detect_mask_kernel<<<1, 256>>>((const unsigned char*)mask);
    pack_all_kernel<<<2496, 256>>>(Wq, Wk, Wv1, Wv2, Wo, W1, W2,
                                   wqkvh, wqkvl, woh, wol, w1h, w1l, w2h, w2l);
    embed_kernel<<<MROWS, DD>>>(x, ea, mask, nW, nb, eW, eb, noe);

    dim3 gN128(1, MROWS/128);
    dim3 gN512(4, MROWS/128);

    for (int l = 0; l < LL; l++) {
        const __nv_bfloat16* wqh = wqkvh + (size_t)l*512*128;
        const __nv_bfloat16* wql = wqkvl + (size_t)l*512*128;
        const __nv_bfloat16* wo_h = woh + (size_t)l*128*128;
        const __nv_bfloat16* wo_l = wol + (size_t)l*128*128;
        const __nv_bfloat16* w1_h = w1h + (size_t)l*512*128;
        const __nv_bfloat16* w1_l = w1l + (size_t)l*512*128;
        const __nv_bfloat16* w2_h = w2h + (size_t)l*128*512;
        const __nv_bfloat16* w2_l = w2l + (size_t)l*128*512;
        const float* bo_l  = bo  + (size_t)l*DD;
        const float* g1_l  = ln1g + (size_t)l*DD;
        const float* b1l_l = ln1b + (size_t)l*DD;
        const float* bf1_l = b1  + (size_t)l*FF;
        const float* bf2_l = b2  + (size_t)l*DD;
        const float* g2_l  = ln2g + (size_t)l*DD;
        const float* b2l_l = ln2b + (size_t)l*DD;

        // fused QKV projection: A = tok (split), C = qkv fp32
        mma_gemm_kernel<<<gN512, 256, GSMEM>>>(tokh, tokl, wqh, wql,
            nullptr, nullptr, nullptr, nullptr, qkv, nullptr, nullptr, 128, 512, 0);

        score_kernel<<<BB*HH*NN, 256>>>();
        softmax_kernel<<<BB*HH*NN, 256>>>();
        attn_o_kernel<<<512, 256, ATTN_SMEM>>>();

        // o-projection + bias + residual(tok) + LN1 -> tok fp32 + split
        mma_gemm_kernel<<<gN128, 256, GSMEM>>>(oh_, ol_, wo_h, wo_l,
            bo_l, tok, g1_l, b1l_l, tok, tokh, tokl, 128, 128, 0);
        // FFN up + relu -> hid split only
        mma_gemm_kernel<<<gN512, 256, GSMEM>>>(tokh, tokl, w1_h, w1_l,
            bf1_l, nullptr, nullptr, nullptr, nullptr, hidh, hidl, 128, 512, 1);
        // FFN down + bias + residual(tok) + LN2 -> tok fp32 + split
        mma_gemm_kernel<<<gN128, 256, GSMEM>>>(hidh, hidl, w2_h, w2_l,
            bf2_l, tok, g2_l, b2l_l, tok, tokh, tokl, 512, 128, 0);
    }

    out_kernel<<<BB*NN, 128>>>(Wout, bout, (float*)d_out);
}